// round 8
// baseline (speedup 1.0000x reference)
#include <cuda_runtime.h>
#include <math.h>
#include <stdint.h>

#define BW 64
#define BO 64
#define TW 32
#define TO 36
#define DD 512
#define SCALE 0.044194173824159216f  // 1/sqrt(512)
#define WSTR 516                     // w row stride
#define USTR 516                     // u row stride (phase 2)
#define OSTR2 520                    // o row stride (phase 4, conflict-free A)
#define ASTR 44                      // att_al row stride (conflict-free B)
#define NTHR 576

// smem layout (float offsets)
#define OFF_W     0          // 32*516 = 16512
#define OFF_UO    16512      // max(40*516, 40*520) = 20800
#define OFF_P2    37312      // 8*1280 = 10240 (phase2 partials [ks][32][40])
#define OFF_ATTC  47552      // 1168 (shifted att for global store)
#define OFF_ATTAL 48720      // 32*44 = 1408 (mma B operand, k-padded)
#define OFF_LGP   50128      // 32*16 = 512
#define OFF_PMAX  50640      // 288
#define OFF_PSUM  50928      // 288
#define OFF_RMAX  51216      // 32
#define OFF_RINV  51248      // 32
#define SMEM_FLOATS 51280    // 205120 bytes

__device__ float g_logits[BW * TW * BO];   // [wb][t][ob]
__device__ float g_partial[BW];

typedef unsigned long long ull;

__device__ __forceinline__ uint32_t f2tf(float x) {
    uint32_t r; asm("cvt.rna.tf32.f32 %0, %1;" : "=r"(r) : "f"(x)); return r;
}
__device__ __forceinline__ void mma_tf32(float* c, const uint32_t* a,
                                         uint32_t b0, uint32_t b1) {
    asm("mma.sync.aligned.m16n8k8.row.col.f32.tf32.tf32.f32 "
        "{%0,%1,%2,%3}, {%4,%5,%6,%7}, {%8,%9}, {%0,%1,%2,%3};"
        : "+f"(c[0]), "+f"(c[1]), "+f"(c[2]), "+f"(c[3])
        : "r"(a[0]), "r"(a[1]), "r"(a[2]), "r"(a[3]), "r"(b0), "r"(b1));
}

extern __shared__ float smem[];

__global__ __launch_bounds__(NTHR, 1)
void cap_main(const float* __restrict__ g_o,
              const float* __restrict__ g_u,
              const float* __restrict__ g_w,
              float* __restrict__ out_att,   // = d_out + 1
              float* __restrict__ out_avo)   // = d_out + 1 + 64*64*32*36
{
    const int ob  = blockIdx.x;
    const int wb  = blockIdx.y;
    const int blk = wb * BO + ob;
    const int tid = threadIdx.x;

    float*  w_s    = smem + OFF_W;
    float*  uo     = smem + OFF_UO;     // u (str 516) then o (str 520)
    float*  p2     = smem + OFF_P2;
    float*  att_cs = smem + OFF_ATTC;
    float*  att_al = smem + OFF_ATTAL;
    float*  lgp    = smem + OFF_LGP;
    float*  pmax   = smem + OFF_PMAX;
    float*  psum   = smem + OFF_PSUM;
    float*  rowmax = smem + OFF_RMAX;
    float*  rowinv = smem + OFF_RINV;

    const int wrp  = tid >> 5;
    const int lane = tid & 31;
    const int g    = lane >> 2;      // mma groupID
    const int tg   = lane & 3;       // mma threadID in group

    // ---------- phase 1: load w (32x512) and u (36x512); zero pads ----------
    for (int idx = tid; idx < TW * 128; idx += NTHR) {
        int t = idx >> 7, c = idx & 127;
        float4 v = reinterpret_cast<const float4*>(g_w)[((size_t)wb * TW + t) * 128 + c];
        *reinterpret_cast<float4*>(&w_s[t * WSTR + 4 * c]) = v;
    }
    for (int idx = tid; idx < TO * 128; idx += NTHR) {
        int o = idx >> 7, c = idx & 127;
        float4 v = reinterpret_cast<const float4*>(g_u)[((size_t)ob * TO + o) * 128 + c];
        *reinterpret_cast<float4*>(&uo[o * USTR + 4 * c]) = v;
    }
    for (int idx = tid; idx < 4 * USTR; idx += NTHR)
        uo[TO * USTR + idx] = 0.f;                 // u rows 36-39 zero
    if (tid < 256) {                               // att_al k-pad cols 36-43
        int t = tid >> 3, j = tid & 7;
        att_al[t * ASTR + 36 + j] = 0.f;
    }
    __syncthreads();

    // ---------- phase 2: scores via tf32 mma (3-term split) -----------------
    if (wrp < 16) {
        const int mt = wrp & 1;
        const int ks = wrp >> 1;

        float c[5][4];
        #pragma unroll
        for (int nt = 0; nt < 5; nt++)
            #pragma unroll
            for (int q = 0; q < 4; q++) c[nt][q] = 0.f;

        const float* wrow0 = w_s + (16 * mt + g) * WSTR;
        const float* wrow1 = wrow0 + 8 * WSTR;

        #pragma unroll 2
        for (int j = 0; j < 8; j++) {
            const int k0 = (ks * 8 + j) * 8;
            float a0 = wrow0[k0 + tg];
            float a1 = wrow1[k0 + tg];
            float a2 = wrow0[k0 + tg + 4];
            float a3 = wrow1[k0 + tg + 4];
            uint32_t ah[4], al[4];
            ah[0] = f2tf(a0); al[0] = __float_as_uint(a0 - __uint_as_float(ah[0]));
            ah[1] = f2tf(a1); al[1] = __float_as_uint(a1 - __uint_as_float(ah[1]));
            ah[2] = f2tf(a2); al[2] = __float_as_uint(a2 - __uint_as_float(ah[2]));
            ah[3] = f2tf(a3); al[3] = __float_as_uint(a3 - __uint_as_float(ah[3]));
            #pragma unroll
            for (int nt = 0; nt < 5; nt++) {
                const float* ur = uo + (8 * nt + g) * USTR + k0;
                float b0 = ur[tg];
                float b1 = ur[tg + 4];
                uint32_t bh0 = f2tf(b0);
                uint32_t bh1 = f2tf(b1);
                uint32_t bl0 = __float_as_uint(b0 - __uint_as_float(bh0));
                uint32_t bl1 = __float_as_uint(b1 - __uint_as_float(bh1));
                mma_tf32(c[nt], ah, bh0, bh1);
                mma_tf32(c[nt], ah, bl0, bl1);
                mma_tf32(c[nt], al, bh0, bh1);
            }
        }
        float* pp = p2 + ks * 1280 + (16 * mt) * 40;
        #pragma unroll
        for (int nt = 0; nt < 5; nt++) {
            int col = 8 * nt + 2 * tg;
            *reinterpret_cast<float2*>(&pp[g * 40 + col])       = make_float2(c[nt][0], c[nt][1]);
            *reinterpret_cast<float2*>(&pp[(g + 8) * 40 + col]) = make_float2(c[nt][2], c[nt][3]);
        }
    }
    __syncthreads();

    // ---------- phase 3: reduce k-slices + softmax over To=36 ---------------
    const int st = tid / 9, sj = tid % 9;      // valid for tid<288
    float sc[4], ee[4];
    if (tid < 288) {
        #pragma unroll
        for (int q = 0; q < 4; q++) {
            int col = 4 * sj + q;
            float s = 0.f;
            #pragma unroll
            for (int ks = 0; ks < 8; ks++) s += p2[ks * 1280 + st * 40 + col];
            sc[q] = s * SCALE;
        }
        pmax[tid] = fmaxf(fmaxf(sc[0], sc[1]), fmaxf(sc[2], sc[3]));
    }
    __syncthreads();
    if (tid < 32) {
        float m = pmax[tid * 9];
        #pragma unroll
        for (int k = 1; k < 9; k++) m = fmaxf(m, pmax[tid * 9 + k]);
        rowmax[tid] = m;
    }
    __syncthreads();
    if (tid < 288) {
        float m = rowmax[st];
        float s = 0.f;
        #pragma unroll
        for (int q = 0; q < 4; q++) { ee[q] = expf(sc[q] - m); s += ee[q]; }
        psum[tid] = s;
    }
    __syncthreads();
    if (tid < 32) {
        float s = 0.f;
        #pragma unroll
        for (int k = 0; k < 9; k++) s += psum[tid * 9 + k];
        rowinv[tid] = 1.f / s;
    }
    __syncthreads();
    if (tid < 288) {
        float inv = rowinv[st];
        #pragma unroll
        for (int q = 0; q < 4; q++) {
            float a = ee[q] * inv;
            att_cs[1 + st * TO + 4 * sj + q]  = a;
            att_al[st * ASTR + 4 * sj + q]    = a;
        }
    }
    __syncthreads();

    // ---------- att store (shifted float4) + phase 4a: o tile (plain) -------
    {
        const size_t ab = (size_t)blk * (TW * TO);
        if (tid < 287) {
            float4 v = *reinterpret_cast<const float4*>(&att_cs[4 + 4 * tid]);
            *reinterpret_cast<float4*>(&out_att[ab + 3 + 4 * tid]) = v;
        } else if (tid == 287) {
            out_att[ab + 0]    = att_cs[1];
            out_att[ab + 1]    = att_cs[2];
            out_att[ab + 2]    = att_cs[3];
            out_att[ab + 1151] = att_cs[1152];
        }
    }
    for (int idx = tid; idx < TO * 128; idx += NTHR) {
        int o = idx >> 7, c = idx & 127;
        float4 v = reinterpret_cast<const float4*>(g_o)[((size_t)ob * TO + o) * 128 + c];
        *reinterpret_cast<float4*>(&uo[o * OSTR2 + 4 * c]) = v;
    }
    for (int idx = tid; idx < 4 * OSTR2; idx += NTHR)
        uo[TO * OSTR2 + idx] = 0.f;                // o rows 36-39 zero
    __syncthreads();

    // ---------- phase 4b: avo via tf32 mma, C[m=d][n=t], logits fused -------
    if (wrp < 16) {
        const int m0 = 32 * wrp;                   // warp's d base (32 cols)
        float lgt[4][2];
        #pragma unroll
        for (int nt = 0; nt < 4; nt++) { lgt[nt][0] = 0.f; lgt[nt][1] = 0.f; }

        #pragma unroll
        for (int mt2 = 0; mt2 < 2; mt2++) {
            const int mb = m0 + 16 * mt2;
            float c[4][4];
            #pragma unroll
            for (int nt = 0; nt < 4; nt++)
                #pragma unroll
                for (int q = 0; q < 4; q++) c[nt][q] = 0.f;

            #pragma unroll
            for (int kk = 0; kk < 5; kk++) {
                const int k0 = 8 * kk;
                float a0 = uo[(k0 + tg)     * OSTR2 + mb + g];
                float a1 = uo[(k0 + tg)     * OSTR2 + mb + g + 8];
                float a2 = uo[(k0 + tg + 4) * OSTR2 + mb + g];
                float a3 = uo[(k0 + tg + 4) * OSTR2 + mb + g + 8];
                uint32_t ah[4], al[4];
                ah[0] = f2tf(a0); al[0] = __float_as_uint(a0 - __uint_as_float(ah[0]));
                ah[1] = f2tf(a1); al[1] = __float_as_uint(a1 - __uint_as_float(ah[1]));
                ah[2] = f2tf(a2); al[2] = __float_as_uint(a2 - __uint_as_float(ah[2]));
                ah[3] = f2tf(a3); al[3] = __float_as_uint(a3 - __uint_as_float(ah[3]));
                #pragma unroll
                for (int nt = 0; nt < 4; nt++) {
                    float b0 = att_al[(8 * nt + g) * ASTR + k0 + tg];
                    float b1 = att_al[(8 * nt + g) * ASTR + k0 + tg + 4];
                    uint32_t bh0 = f2tf(b0);
                    uint32_t bh1 = f2tf(b1);
                    uint32_t bl0 = __float_as_uint(b0 - __uint_as_float(bh0));
                    uint32_t bl1 = __float_as_uint(b1 - __uint_as_float(bh1));
                    mma_tf32(c[nt], ah, bh0, bh1);
                    mma_tf32(c[nt], ah, bl0, bl1);
                    mma_tf32(c[nt], al, bh0, bh1);
                }
            }

            // store + logits
            const int d0 = mb + g;
            #pragma unroll
            for (int nt = 0; nt < 4; nt++) {
                const int t0 = 8 * nt + 2 * tg;
                float* r0 = out_avo + ((size_t)blk * TW + t0) * DD;
                float* r1 = out_avo + ((size_t)blk * TW + t0 + 1) * DD;
                r0[d0]     = c[nt][0];
                r1[d0]     = c[nt][1];
                r0[d0 + 8] = c[nt][2];
                r1[d0 + 8] = c[nt][3];
                lgt[nt][0] += c[nt][0] * w_s[t0 * WSTR + d0]
                            + c[nt][2] * w_s[t0 * WSTR + d0 + 8];
                lgt[nt][1] += c[nt][1] * w_s[(t0 + 1) * WSTR + d0]
                            + c[nt][3] * w_s[(t0 + 1) * WSTR + d0 + 8];
            }
        }
        // reduce over g (lane = 4g+tg): xor masks 4,8,16
        #pragma unroll
        for (int s = 4; s < 32; s <<= 1)
            #pragma unroll
            for (int nt = 0; nt < 4; nt++) {
                lgt[nt][0] += __shfl_xor_sync(0xffffffffu, lgt[nt][0], s);
                lgt[nt][1] += __shfl_xor_sync(0xffffffffu, lgt[nt][1], s);
            }
        if (g == 0) {
            #pragma unroll
            for (int nt = 0; nt < 4; nt++) {
                lgp[(8 * nt + 2 * tg)     * 16 + wrp] = lgt[nt][0];
                lgp[(8 * nt + 2 * tg + 1) * 16 + wrp] = lgt[nt][1];
            }
        }
    }
    __syncthreads();

    if (tid < 32) {
        float s = 0.f;
        #pragma unroll
        for (int k = 0; k < 16; k++) s += lgp[tid * 16 + k];
        g_logits[(wb * TW + tid) * BO + ob] = s;
    }
}

// log-softmax over Bo + masked diagonal accumulation, one block per wb
__global__ void cap_loss1(const int* __restrict__ g_mask)
{
    const int wb   = blockIdx.x;
    const int wid  = threadIdx.x >> 5;
    const int lane = threadIdx.x & 31;
    __shared__ float warp_part[8];

    float keepl = 1.f - (float)g_mask[wb * TW + lane];
    float nk = keepl;
    #pragma unroll
    for (int s = 16; s; s >>= 1) nk += __shfl_xor_sync(0xffffffffu, nk, s);

    float acc = 0.f;
    #pragma unroll
    for (int k = 0; k < 4; k++) {
        int t = wid + 8 * k;
        const float* row = g_logits + (wb * TW + t) * BO;
        float v0 = row[lane], v1 = row[lane + 32];
        float m = fmaxf(v0, v1);
        #pragma unroll
        for (int s = 16; s; s >>= 1) m = fmaxf(m, __shfl_xor_sync(0xffffffffu, m, s));
        float e = expf(v0 - m) + expf(v1 - m);
        #pragma unroll
        for (int s = 16; s; s >>= 1) e += __shfl_xor_sync(0xffffffffu, e, s);
        float lse = m + logf(e);
        float dv = (wb < 32) ? __shfl_sync(0xffffffffu, v0, wb)
                             : __shfl_sync(0xffffffffu, v1, wb - 32);
        float kt = 1.f - (float)g_mask[wb * TW + t];
        acc += kt * (dv - lse);
    }
    if (lane == 0) warp_part[wid] = acc;
    __syncthreads();
    if (threadIdx.x == 0) {
        float s = 0.f;
        #pragma unroll
        for (int k = 0; k < 8; k++) s += warp_part[k];
        g_partial[wb] = s / (nk + 1e-6f);
    }
}

__global__ void cap_loss2(float* __restrict__ out)
{
    __shared__ float sh[64];
    sh[threadIdx.x] = g_partial[threadIdx.x];
    __syncthreads();
    if (threadIdx.x == 0) {
        float s = 0.f;
        #pragma unroll
        for (int k = 0; k < 64; k++) s += sh[k];
        out[0] = -s / 64.f;
    }
}

extern "C" void kernel_launch(void* const* d_in, const int* in_sizes, int n_in,
                              void* d_out, int out_size)
{
    const float* g_o    = (const float*)d_in[0];
    const float* g_u    = (const float*)d_in[1];
    const float* g_w    = (const float*)d_in[2];
    const int*   g_mask = (const int*)d_in[3];

    float* out     = (float*)d_out;
    float* out_att = out + 1;
    float* out_avo = out_att + (size_t)BW * BO * TW * TO;

    const size_t SMEM_BYTES = (size_t)SMEM_FLOATS * sizeof(float);
    cudaFuncSetAttribute(cap_main, cudaFuncAttributeMaxDynamicSharedMemorySize,
                         (int)SMEM_BYTES);

    dim3 grid(BO, BW);
    cap_main<<<grid, NTHR, SMEM_BYTES>>>(g_o, g_u, g_w, out_att, out_avo);
    cap_loss1<<<BW, 256>>>(g_mask);
    cap_loss2<<<1, 64>>>(out);
}

// round 9
// speedup vs baseline: 1.3977x; 1.3977x over previous
#include <cuda_runtime.h>
#include <math.h>
#include <stdint.h>

#define BW 64
#define BO 64
#define TW 32
#define TO 36
#define DD 512
#define SCALE 0.044194173824159216f  // 1/sqrt(512)
#define WSTR 516                     // w row stride
#define USTR 516                     // u row stride (phase 2)
#define OSTR2 520                    // o row stride (phase 4), +1 shifted
#define ASTR 44                      // att_al row stride
#define NTHR 576

// smem layout (float offsets)
#define OFF_W     0          // 32*516 = 16512
#define OFF_UO    16512      // max(40*516, 40*520) = 20800
#define OFF_P2    37312      // 8*1280 = 10240
#define OFF_ATTC  47552      // 1168
#define OFF_ATTAL 48720      // 32*44 = 1408
#define OFF_LGP   50128      // 32*16 = 512
#define OFF_LGP2  50640      // 32*7 = 224
#define OFF_PMAX  50864      // 288
#define OFF_PSUM  51152      // 288
#define OFF_RMAX  51440      // 32
#define OFF_RINV  51472      // 32
#define SMEM_FLOATS 51504    // 206016 bytes

__device__ float g_logits[BW * TW * BO];   // [wb][t][ob]
__device__ float g_partial[BW];

__device__ __forceinline__ uint32_t f2tf(float x) {
    uint32_t r; asm("cvt.rna.tf32.f32 %0, %1;" : "=r"(r) : "f"(x)); return r;
}
__device__ __forceinline__ void mma_tf32(float* c, const uint32_t* a,
                                         uint32_t b0, uint32_t b1) {
    asm("mma.sync.aligned.m16n8k8.row.col.f32.tf32.tf32.f32 "
        "{%0,%1,%2,%3}, {%4,%5,%6,%7}, {%8,%9}, {%0,%1,%2,%3};"
        : "+f"(c[0]), "+f"(c[1]), "+f"(c[2]), "+f"(c[3])
        : "r"(a[0]), "r"(a[1]), "r"(a[2]), "r"(a[3]), "r"(b0), "r"(b1));
}

extern __shared__ float smem[];

__global__ __launch_bounds__(NTHR, 1)
void cap_main(const float* __restrict__ g_o,
              const float* __restrict__ g_u,
              const float* __restrict__ g_w,
              float* __restrict__ out_att,   // = d_out + 1
              float* __restrict__ out_avo)   // = d_out + 1 + 64*64*32*36
{
    const int ob  = blockIdx.x;
    const int wb  = blockIdx.y;
    const int blk = wb * BO + ob;
    const int tid = threadIdx.x;

    float*  w_s    = smem + OFF_W;
    float*  uo     = smem + OFF_UO;     // u (str 516) then o (str 520, +1 shift)
    float*  p2     = smem + OFF_P2;
    float*  att_cs = smem + OFF_ATTC;
    float*  att_al = smem + OFF_ATTAL;
    float*  lgp    = smem + OFF_LGP;
    float*  lgp2   = smem + OFF_LGP2;
    float*  pmax   = smem + OFF_PMAX;
    float*  psum   = smem + OFF_PSUM;
    float*  rowmax = smem + OFF_RMAX;
    float*  rowinv = smem + OFF_RINV;

    const int wrp  = tid >> 5;
    const int lane = tid & 31;
    const int g    = lane >> 2;      // mma groupID
    const int tg   = lane & 3;       // mma threadID in group

    // ---------- phase 1: load w (32x512) and u (36x512); zero pads ----------
    for (int idx = tid; idx < TW * 128; idx += NTHR) {
        int t = idx >> 7, c = idx & 127;
        float4 v = reinterpret_cast<const float4*>(g_w)[((size_t)wb * TW + t) * 128 + c];
        *reinterpret_cast<float4*>(&w_s[t * WSTR + 4 * c]) = v;
    }
    if (tid < 128) {                               // w pad cols 512-515 zero
        int t = tid >> 2, j = tid & 3;
        w_s[t * WSTR + 512 + j] = 0.f;
    }
    for (int idx = tid; idx < TO * 128; idx += NTHR) {
        int o = idx >> 7, c = idx & 127;
        float4 v = reinterpret_cast<const float4*>(g_u)[((size_t)ob * TO + o) * 128 + c];
        *reinterpret_cast<float4*>(&uo[o * USTR + 4 * c]) = v;
    }
    for (int idx = tid; idx < 4 * USTR; idx += NTHR)
        uo[TO * USTR + idx] = 0.f;                 // u rows 36-39 zero
    if (tid < 256) {                               // att_al k-pad cols 36-43
        int t = tid >> 3, j = tid & 7;
        att_al[t * ASTR + 36 + j] = 0.f;
    }
    __syncthreads();

    // ---------- phase 2: scores via tf32 mma (3-term split) -----------------
    if (wrp < 16) {
        const int mt = wrp & 1;
        const int ks = wrp >> 1;

        float c[5][4];
        #pragma unroll
        for (int nt = 0; nt < 5; nt++)
            #pragma unroll
            for (int q = 0; q < 4; q++) c[nt][q] = 0.f;

        const float* wrow0 = w_s + (16 * mt + g) * WSTR;
        const float* wrow1 = wrow0 + 8 * WSTR;

        #pragma unroll 2
        for (int j = 0; j < 8; j++) {
            const int k0 = (ks * 8 + j) * 8;
            float a0 = wrow0[k0 + tg];
            float a1 = wrow1[k0 + tg];
            float a2 = wrow0[k0 + tg + 4];
            float a3 = wrow1[k0 + tg + 4];
            uint32_t ah[4], al[4];
            ah[0] = f2tf(a0); al[0] = __float_as_uint(a0 - __uint_as_float(ah[0]));
            ah[1] = f2tf(a1); al[1] = __float_as_uint(a1 - __uint_as_float(ah[1]));
            ah[2] = f2tf(a2); al[2] = __float_as_uint(a2 - __uint_as_float(ah[2]));
            ah[3] = f2tf(a3); al[3] = __float_as_uint(a3 - __uint_as_float(ah[3]));
            #pragma unroll
            for (int nt = 0; nt < 5; nt++) {
                const float* ur = uo + (8 * nt + g) * USTR + k0;
                float b0 = ur[tg];
                float b1 = ur[tg + 4];
                uint32_t bh0 = f2tf(b0);
                uint32_t bh1 = f2tf(b1);
                uint32_t bl0 = __float_as_uint(b0 - __uint_as_float(bh0));
                uint32_t bl1 = __float_as_uint(b1 - __uint_as_float(bh1));
                mma_tf32(c[nt], ah, bh0, bh1);
                mma_tf32(c[nt], ah, bl0, bl1);
                mma_tf32(c[nt], al, bh0, bh1);
            }
        }
        float* pp = p2 + ks * 1280 + (16 * mt) * 40;
        #pragma unroll
        for (int nt = 0; nt < 5; nt++) {
            int col = 8 * nt + 2 * tg;
            *reinterpret_cast<float2*>(&pp[g * 40 + col])       = make_float2(c[nt][0], c[nt][1]);
            *reinterpret_cast<float2*>(&pp[(g + 8) * 40 + col]) = make_float2(c[nt][2], c[nt][3]);
        }
    }
    __syncthreads();

    // ---------- phase 3: reduce k-slices + softmax over To=36 ---------------
    const int st = tid / 9, sj = tid % 9;      // valid for tid<288
    float sc[4], ee[4];
    if (tid < 288) {
        #pragma unroll
        for (int q = 0; q < 4; q++) {
            int col = 4 * sj + q;
            float s = 0.f;
            #pragma unroll
            for (int ks = 0; ks < 8; ks++) s += p2[ks * 1280 + st * 40 + col];
            sc[q] = s * SCALE;
        }
        pmax[tid] = fmaxf(fmaxf(sc[0], sc[1]), fmaxf(sc[2], sc[3]));
    }
    __syncthreads();
    if (tid < 32) {
        float m = pmax[tid * 9];
        #pragma unroll
        for (int k = 1; k < 9; k++) m = fmaxf(m, pmax[tid * 9 + k]);
        rowmax[tid] = m;
    }
    __syncthreads();
    if (tid < 288) {
        float m = rowmax[st];
        float s = 0.f;
        #pragma unroll
        for (int q = 0; q < 4; q++) { ee[q] = expf(sc[q] - m); s += ee[q]; }
        psum[tid] = s;
    }
    __syncthreads();
    if (tid < 32) {
        float s = 0.f;
        #pragma unroll
        for (int k = 0; k < 9; k++) s += psum[tid * 9 + k];
        rowinv[tid] = 1.f / s;
    }
    __syncthreads();
    if (tid < 288) {
        float inv = rowinv[st];
        #pragma unroll
        for (int q = 0; q < 4; q++) {
            float a = ee[q] * inv;
            att_cs[1 + st * TO + 4 * sj + q]  = a;
            att_al[st * ASTR + 4 * sj + q]    = a;
        }
    }
    __syncthreads();

    // ---------- att store + phase 4a: o tile (stride 520, +1 shift) ---------
    {
        const size_t ab = (size_t)blk * (TW * TO);
        if (tid < 287) {
            float4 v = *reinterpret_cast<const float4*>(&att_cs[4 + 4 * tid]);
            *reinterpret_cast<float4*>(&out_att[ab + 3 + 4 * tid]) = v;
        } else if (tid == 287) {
            out_att[ab + 0]    = att_cs[1];
            out_att[ab + 1]    = att_cs[2];
            out_att[ab + 2]    = att_cs[3];
            out_att[ab + 1151] = att_cs[1152];
        }
    }
    for (int task = tid; task < TO * 127; task += NTHR) {
        int o = task / 127, k = task % 127;
        const float* gr = g_o + ((size_t)ob * TO + o) * 512;
        float4 A  = *reinterpret_cast<const float4*>(&gr[4 * k]);
        float4 Bv = *reinterpret_cast<const float4*>(&gr[4 * k + 4]);
        *reinterpret_cast<float4*>(&uo[o * OSTR2 + 4 + 4 * k]) =
            make_float4(A.w, Bv.x, Bv.y, Bv.z);
    }
    if (tid < 144) {
        int o = tid / 4, e = tid % 4;
        const float* gr = g_o + ((size_t)ob * TO + o) * 512;
        if (e < 3) uo[o * OSTR2 + 1 + e] = gr[e];
        else       uo[o * OSTR2 + 512]   = gr[511];
    }
    for (int idx = tid; idx < 4 * OSTR2; idx += NTHR)
        uo[TO * OSTR2 + idx] = 0.f;                // o rows 36-39 full zero
    for (int idx = tid; idx < TO * 7; idx += NTHR) {
        int o = idx / 7, cc = idx % 7;             // o pad cols 513-519 zero
        uo[o * OSTR2 + 513 + cc] = 0.f;
    }
    __syncthreads();

    // ---------- phase 4b: avo via tf32 mma, d-strips shifted by 7 -----------
    if (wrp < 16) {
        const int m0 = 7 + 32 * wrp;               // warp d base
        float lgt[4][2];
        #pragma unroll
        for (int nt = 0; nt < 4; nt++) { lgt[nt][0] = 0.f; lgt[nt][1] = 0.f; }

        #pragma unroll
        for (int mt2 = 0; mt2 < 2; mt2++) {
            const int mb = m0 + 16 * mt2;
            float c[4][4];
            #pragma unroll
            for (int nt = 0; nt < 4; nt++)
                #pragma unroll
                for (int q = 0; q < 4; q++) c[nt][q] = 0.f;

            #pragma unroll
            for (int kk = 0; kk < 5; kk++) {
                const int k0 = 8 * kk;
                const float* ab_ = uo + (k0 + tg) * OSTR2 + 1 + mb + g;
                float a0 = ab_[0];
                float a1 = ab_[8];
                float a2 = ab_[4 * OSTR2];
                float a3 = ab_[4 * OSTR2 + 8];
                uint32_t ah[4], al[4];
                ah[0] = f2tf(a0); al[0] = __float_as_uint(a0 - __uint_as_float(ah[0]));
                ah[1] = f2tf(a1); al[1] = __float_as_uint(a1 - __uint_as_float(ah[1]));
                ah[2] = f2tf(a2); al[2] = __float_as_uint(a2 - __uint_as_float(ah[2]));
                ah[3] = f2tf(a3); al[3] = __float_as_uint(a3 - __uint_as_float(ah[3]));
                #pragma unroll
                for (int nt = 0; nt < 4; nt++) {
                    float b0 = att_al[(8 * nt + g) * ASTR + k0 + tg];
                    float b1 = att_al[(8 * nt + g) * ASTR + k0 + tg + 4];
                    uint32_t bh0 = f2tf(b0);
                    uint32_t bh1 = f2tf(b1);
                    uint32_t bl0 = __float_as_uint(b0 - __uint_as_float(bh0));
                    uint32_t bl1 = __float_as_uint(b1 - __uint_as_float(bh1));
                    mma_tf32(c[nt], ah, bh0, bh1);
                    mma_tf32(c[nt], ah, bl0, bl1);
                    mma_tf32(c[nt], al, bh0, bh1);
                }
            }

            const int d0 = mb + g;                 // d0 in [7, 511)
            const bool hi_ok = (d0 + 8 < 512);
            #pragma unroll
            for (int nt = 0; nt < 4; nt++) {
                const int t0 = 8 * nt + 2 * tg;
                float* r0 = out_avo + ((size_t)blk * TW + t0) * DD;
                float* r1 = r0 + DD;
                r0[d0] = c[nt][0];
                r1[d0] = c[nt][1];
                lgt[nt][0] += c[nt][0] * w_s[t0 * WSTR + d0];
                lgt[nt][1] += c[nt][1] * w_s[(t0 + 1) * WSTR + d0];
                if (hi_ok) {
                    r0[d0 + 8] = c[nt][2];
                    r1[d0 + 8] = c[nt][3];
                    lgt[nt][0] += c[nt][2] * w_s[t0 * WSTR + d0 + 8];
                    lgt[nt][1] += c[nt][3] * w_s[(t0 + 1) * WSTR + d0 + 8];
                }
            }
        }
        // reduce over g (lane = 4g+tg): xor masks 4,8,16
        #pragma unroll
        for (int s = 4; s < 32; s <<= 1)
            #pragma unroll
            for (int nt = 0; nt < 4; nt++) {
                lgt[nt][0] += __shfl_xor_sync(0xffffffffu, lgt[nt][0], s);
                lgt[nt][1] += __shfl_xor_sync(0xffffffffu, lgt[nt][1], s);
            }
        if (g == 0) {
            #pragma unroll
            for (int nt = 0; nt < 4; nt++) {
                lgp[(8 * nt + 2 * tg)     * 16 + wrp] = lgt[nt][0];
                lgp[(8 * nt + 2 * tg + 1) * 16 + wrp] = lgt[nt][1];
            }
        }
    } else {
        // warps 16-17: edge columns d in [0,7), 32 t rows = 224 tasks
        const int base = tid - 512;
        #pragma unroll
        for (int rep = 0; rep < 4; rep++) {
            int task = base + 64 * rep;
            if (task < 224) {
                int t = task / 7, e = task % 7;
                float acc = 0.f;
                #pragma unroll 4
                for (int o = 0; o < TO; o++)
                    acc += att_al[t * ASTR + o] * uo[o * OSTR2 + 1 + e];
                out_avo[((size_t)blk * TW + t) * DD + e] = acc;
                lgp2[task] = acc * w_s[t * WSTR + e];
            }
        }
    }
    __syncthreads();

    if (tid < 32) {
        float s = 0.f;
        #pragma unroll
        for (int k = 0; k < 16; k++) s += lgp[tid * 16 + k];
        #pragma unroll
        for (int e = 0; e < 7; e++)  s += lgp2[tid * 7 + e];
        g_logits[(wb * TW + tid) * BO + ob] = s;
    }
}

// log-softmax over Bo + masked diagonal accumulation, one block per wb
__global__ void cap_loss1(const int* __restrict__ g_mask)
{
    const int wb   = blockIdx.x;
    const int wid  = threadIdx.x >> 5;
    const int lane = threadIdx.x & 31;
    __shared__ float warp_part[8];

    float keepl = 1.f - (float)g_mask[wb * TW + lane];
    float nk = keepl;
    #pragma unroll
    for (int s = 16; s; s >>= 1) nk += __shfl_xor_sync(0xffffffffu, nk, s);

    float acc = 0.f;
    #pragma unroll
    for (int k = 0; k < 4; k++) {
        int t = wid + 8 * k;
        const float* row = g_logits + (wb * TW + t) * BO;
        float v0 = row[lane], v1 = row[lane + 32];
        float m = fmaxf(v0, v1);
        #pragma unroll
        for (int s = 16; s; s >>= 1) m = fmaxf(m, __shfl_xor_sync(0xffffffffu, m, s));
        float e = expf(v0 - m) + expf(v1 - m);
        #pragma unroll
        for (int s = 16; s; s >>= 1) e += __shfl_xor_sync(0xffffffffu, e, s);
        float lse = m + logf(e);
        float dv = (wb < 32) ? __shfl_sync(0xffffffffu, v0, wb)
                             : __shfl_sync(0xffffffffu, v1, wb - 32);
        float kt = 1.f - (float)g_mask[wb * TW + t];
        acc += kt * (dv - lse);
    }
    if (lane == 0) warp_part[wid] = acc;
    __syncthreads();
    if (threadIdx.x == 0) {
        float s = 0.f;
        #pragma unroll
        for (int k = 0; k < 8; k++) s += warp_part[k];
        g_partial[wb] = s / (nk + 1e-6f);
    }
}

__global__ void cap_loss2(float* __restrict__ out)
{
    __shared__ float sh[64];
    sh[threadIdx.x] = g_partial[threadIdx.x];
    __syncthreads();
    if (threadIdx.x == 0) {
        float s = 0.f;
        #pragma unroll
        for (int k = 0; k < 64; k++) s += sh[k];
        out[0] = -s / 64.f;
    }
}

extern "C" void kernel_launch(void* const* d_in, const int* in_sizes, int n_in,
                              void* d_out, int out_size)
{
    const float* g_o    = (const float*)d_in[0];
    const float* g_u    = (const float*)d_in[1];
    const float* g_w    = (const float*)d_in[2];
    const int*   g_mask = (const int*)d_in[3];

    float* out     = (float*)d_out;
    float* out_att = out + 1;
    float* out_avo = out_att + (size_t)BW * BO * TW * TO;

    const size_t SMEM_BYTES = (size_t)SMEM_FLOATS * sizeof(float);
    cudaFuncSetAttribute(cap_main, cudaFuncAttributeMaxDynamicSharedMemorySize,
                         (int)SMEM_BYTES);

    dim3 grid(BO, BW);
    cap_main<<<grid, NTHR, SMEM_BYTES>>>(g_o, g_u, g_w, out_att, out_avo);
    cap_loss1<<<BW, 256>>>(g_mask);
    cap_loss2<<<1, 64>>>(out);
}

// round 11
// speedup vs baseline: 1.4172x; 1.0139x over previous
#include <cuda_runtime.h>
#include <math.h>
#include <stdint.h>

#define BW 64
#define BO 64
#define TW 32
#define TO 36
#define DD 512
#define SCALE 0.044194173824159216f  // 1/sqrt(512)
#define WSTR 516                     // w row stride
#define USTR 516                     // u row stride (phase 2)
#define OSTR2 520                    // o row stride (phase 4), +1 shifted
#define ASTR 44                      // att_al row stride
#define NTHR 576

// smem layout (float offsets)
#define OFF_W     0          // 32*516 = 16512
#define OFF_UO    16512      // max(40*516, 40*520) = 20800
#define OFF_P2    37312      // 8*1280 = 10240
#define OFF_ATTC  47552      // 1168
#define OFF_ATTAL 48720      // 32*44 = 1408
#define OFF_LGP   50128      // 32*16 = 512
#define OFF_LGP2  50640      // 32*7 = 224
#define OFF_PMAX  50864      // 288
#define OFF_PSUM  51152      // 288
#define OFF_RMAX  51440      // 32
#define OFF_RINV  51472      // 32
#define SMEM_FLOATS 51504    // 206016 bytes

__device__ float g_logits[BW * TW * BO];   // [wb][t][ob]
__device__ float g_partial[BW];

__device__ __forceinline__ uint32_t f2tf(float x) {
    uint32_t r; asm("cvt.rna.tf32.f32 %0, %1;" : "=r"(r) : "f"(x)); return r;
}
__device__ __forceinline__ void mma_tf32(float* c, const uint32_t* a,
                                         uint32_t b0, uint32_t b1) {
    asm("mma.sync.aligned.m16n8k8.row.col.f32.tf32.tf32.f32 "
        "{%0,%1,%2,%3}, {%4,%5,%6,%7}, {%8,%9}, {%0,%1,%2,%3};"
        : "+f"(c[0]), "+f"(c[1]), "+f"(c[2]), "+f"(c[3])
        : "r"(a[0]), "r"(a[1]), "r"(a[2]), "r"(a[3]), "r"(b0), "r"(b1));
}

extern __shared__ float smem[];

__global__ __launch_bounds__(NTHR, 1)
void cap_main(const float* __restrict__ g_o,
              const float* __restrict__ g_u,
              const float* __restrict__ g_w,
              float* __restrict__ out_att,   // = d_out + 1
              float* __restrict__ out_avo)   // = d_out + 1 + 64*64*32*36
{
    const int ob  = blockIdx.x;
    const int wb  = blockIdx.y;
    const int blk = wb * BO + ob;
    const int tid = threadIdx.x;

    float*  w_s    = smem + OFF_W;
    float*  uo     = smem + OFF_UO;     // u (str 516) then o (str 520, +1 shift)
    float*  p2     = smem + OFF_P2;
    float*  att_cs = smem + OFF_ATTC;
    float*  att_al = smem + OFF_ATTAL;
    float*  lgp    = smem + OFF_LGP;
    float*  lgp2   = smem + OFF_LGP2;
    float*  pmax   = smem + OFF_PMAX;
    float*  psum   = smem + OFF_PSUM;
    float*  rowmax = smem + OFF_RMAX;
    float*  rowinv = smem + OFF_RINV;

    const int wrp  = tid >> 5;
    const int lane = tid & 31;
    const int g    = lane >> 2;      // mma groupID
    const int tg   = lane & 3;       // mma threadID in group

    // ---------- phase 1: load w (32x512) and u (36x512); zero pads ----------
    for (int idx = tid; idx < TW * 128; idx += NTHR) {
        int t = idx >> 7, c = idx & 127;
        float4 v = reinterpret_cast<const float4*>(g_w)[((size_t)wb * TW + t) * 128 + c];
        *reinterpret_cast<float4*>(&w_s[t * WSTR + 4 * c]) = v;
    }
    if (tid < 128) {                               // w pad cols 512-515 zero
        int t = tid >> 2, j = tid & 3;
        w_s[t * WSTR + 512 + j] = 0.f;
    }
    for (int idx = tid; idx < TO * 128; idx += NTHR) {
        int o = idx >> 7, c = idx & 127;
        float4 v = reinterpret_cast<const float4*>(g_u)[((size_t)ob * TO + o) * 128 + c];
        *reinterpret_cast<float4*>(&uo[o * USTR + 4 * c]) = v;
    }
    for (int idx = tid; idx < 4 * USTR; idx += NTHR)
        uo[TO * USTR + idx] = 0.f;                 // u rows 36-39 zero
    if (tid < 256) {                               // att_al k-pad cols 36-43
        int t = tid >> 3, j = tid & 7;
        att_al[t * ASTR + 36 + j] = 0.f;
    }
    __syncthreads();

    // ---------- phase 2: scores via tf32 mma (3-term split) -----------------
    if (wrp < 16) {
        const int mt = wrp & 1;
        const int ks = wrp >> 1;

        float c[5][4];
        #pragma unroll
        for (int nt = 0; nt < 5; nt++)
            #pragma unroll
            for (int q = 0; q < 4; q++) c[nt][q] = 0.f;

        const float* wrow0 = w_s + (16 * mt + g) * WSTR;
        const float* wrow1 = wrow0 + 8 * WSTR;

        #pragma unroll 2
        for (int j = 0; j < 8; j++) {
            const int k0 = (ks * 8 + j) * 8;
            float a0 = wrow0[k0 + tg];
            float a1 = wrow1[k0 + tg];
            float a2 = wrow0[k0 + tg + 4];
            float a3 = wrow1[k0 + tg + 4];
            uint32_t ah[4], al[4];
            ah[0] = f2tf(a0); al[0] = __float_as_uint(a0 - __uint_as_float(ah[0]));
            ah[1] = f2tf(a1); al[1] = __float_as_uint(a1 - __uint_as_float(ah[1]));
            ah[2] = f2tf(a2); al[2] = __float_as_uint(a2 - __uint_as_float(ah[2]));
            ah[3] = f2tf(a3); al[3] = __float_as_uint(a3 - __uint_as_float(ah[3]));
            #pragma unroll
            for (int nt = 0; nt < 5; nt++) {
                const float* ur = uo + (8 * nt + g) * USTR + k0;
                float b0 = ur[tg];
                float b1 = ur[tg + 4];
                uint32_t bh0 = f2tf(b0);
                uint32_t bh1 = f2tf(b1);
                uint32_t bl0 = __float_as_uint(b0 - __uint_as_float(bh0));
                uint32_t bl1 = __float_as_uint(b1 - __uint_as_float(bh1));
                mma_tf32(c[nt], ah, bh0, bh1);
                mma_tf32(c[nt], ah, bl0, bl1);
                mma_tf32(c[nt], al, bh0, bh1);
            }
        }
        float* pp = p2 + ks * 1280 + (16 * mt) * 40;
        #pragma unroll
        for (int nt = 0; nt < 5; nt++) {
            int col = 8 * nt + 2 * tg;
            *reinterpret_cast<float2*>(&pp[g * 40 + col])       = make_float2(c[nt][0], c[nt][1]);
            *reinterpret_cast<float2*>(&pp[(g + 8) * 40 + col]) = make_float2(c[nt][2], c[nt][3]);
        }
    }
    __syncthreads();

    // ---------- phase 4a (moved early): o tile load, overlaps softmax -------
    // u region is dead after phase 2; issue o LDGs now so their latency hides
    // under the phase-3 barrier chain.
    for (int task = tid; task < TO * 127; task += NTHR) {
        int o = task / 127, k = task % 127;
        const float* gr = g_o + ((size_t)ob * TO + o) * 512;
        float4 A  = *reinterpret_cast<const float4*>(&gr[4 * k]);
        float4 Bv = *reinterpret_cast<const float4*>(&gr[4 * k + 4]);
        *reinterpret_cast<float4*>(&uo[o * OSTR2 + 4 + 4 * k]) =
            make_float4(A.w, Bv.x, Bv.y, Bv.z);
    }
    if (tid < 144) {
        int o = tid / 4, e = tid % 4;
        const float* gr = g_o + ((size_t)ob * TO + o) * 512;
        if (e < 3) uo[o * OSTR2 + 1 + e] = gr[e];
        else       uo[o * OSTR2 + 512]   = gr[511];
    }
    for (int idx = tid; idx < 4 * OSTR2; idx += NTHR)
        uo[TO * OSTR2 + idx] = 0.f;                // o rows 36-39 full zero
    for (int idx = tid; idx < TO * 7; idx += NTHR) {
        int o = idx / 7, cc = idx % 7;             // o pad cols 513-519 zero
        uo[o * OSTR2 + 513 + cc] = 0.f;
    }

    // ---------- phase 3: reduce k-slices + softmax over To=36 ---------------
    const int st = tid / 9, sj = tid % 9;      // valid for tid<288
    float sc[4], ee[4];
    if (tid < 288) {
        #pragma unroll
        for (int q = 0; q < 4; q++) {
            int col = 4 * sj + q;
            float s = 0.f;
            #pragma unroll
            for (int ks = 0; ks < 8; ks++) s += p2[ks * 1280 + st * 40 + col];
            sc[q] = s * SCALE;
        }
        pmax[tid] = fmaxf(fmaxf(sc[0], sc[1]), fmaxf(sc[2], sc[3]));
    }
    __syncthreads();
    if (tid < 32) {
        float m = pmax[tid * 9];
        #pragma unroll
        for (int k = 1; k < 9; k++) m = fmaxf(m, pmax[tid * 9 + k]);
        rowmax[tid] = m;
    }
    __syncthreads();
    if (tid < 288) {
        float m = rowmax[st];
        float s = 0.f;
        #pragma unroll
        for (int q = 0; q < 4; q++) { ee[q] = expf(sc[q] - m); s += ee[q]; }
        psum[tid] = s;
    }
    __syncthreads();
    if (tid < 32) {
        float s = 0.f;
        #pragma unroll
        for (int k = 0; k < 9; k++) s += psum[tid * 9 + k];
        rowinv[tid] = 1.f / s;
    }
    __syncthreads();
    if (tid < 288) {
        float inv = rowinv[st];
        #pragma unroll
        for (int q = 0; q < 4; q++) {
            float a = ee[q] * inv;
            att_cs[1 + st * TO + 4 * sj + q]  = a;
            att_al[st * ASTR + 4 * sj + q]    = a;
        }
    }
    __syncthreads();

    // ---------- att global store (shifted float4) ---------------------------
    {
        const size_t ab = (size_t)blk * (TW * TO);
        if (tid < 287) {
            float4 v = *reinterpret_cast<const float4*>(&att_cs[4 + 4 * tid]);
            *reinterpret_cast<float4*>(&out_att[ab + 3 + 4 * tid]) = v;
        } else if (tid == 287) {
            out_att[ab + 0]    = att_cs[1];
            out_att[ab + 1]    = att_cs[2];
            out_att[ab + 2]    = att_cs[3];
            out_att[ab + 1151] = att_cs[1152];
        }
    }
    __syncthreads();

    // ---------- phase 4b: avo via tf32 mma, kk-outer (B shared over mt2) ----
    if (wrp < 16) {
        const int m0 = 7 + 32 * wrp;               // warp d base

        float c[2][4][4];
        #pragma unroll
        for (int mt2 = 0; mt2 < 2; mt2++)
            #pragma unroll
            for (int nt = 0; nt < 4; nt++)
                #pragma unroll
                for (int q = 0; q < 4; q++) c[mt2][nt][q] = 0.f;

        #pragma unroll
        for (int kk = 0; kk < 5; kk++) {
            const int k0 = 8 * kk;
            // B (att) split once per kk, shared across both mt2 tiles
            uint32_t bh[4][2], bl[4][2];
            #pragma unroll
            for (int nt = 0; nt < 4; nt++) {
                float b0 = att_al[(8 * nt + g) * ASTR + k0 + tg];
                float b1 = att_al[(8 * nt + g) * ASTR + k0 + tg + 4];
                bh[nt][0] = f2tf(b0);
                bh[nt][1] = f2tf(b1);
                bl[nt][0] = __float_as_uint(b0 - __uint_as_float(bh[nt][0]));
                bl[nt][1] = __float_as_uint(b1 - __uint_as_float(bh[nt][1]));
            }
            #pragma unroll
            for (int mt2 = 0; mt2 < 2; mt2++) {
                const int mb = m0 + 16 * mt2;
                const float* ab_ = uo + (k0 + tg) * OSTR2 + 1 + mb + g;
                float a0 = ab_[0];
                float a1 = ab_[8];
                float a2 = ab_[4 * OSTR2];
                float a3 = ab_[4 * OSTR2 + 8];
                uint32_t ah[4], al[4];
                ah[0] = f2tf(a0); al[0] = __float_as_uint(a0 - __uint_as_float(ah[0]));
                ah[1] = f2tf(a1); al[1] = __float_as_uint(a1 - __uint_as_float(ah[1]));
                ah[2] = f2tf(a2); al[2] = __float_as_uint(a2 - __uint_as_float(ah[2]));
                ah[3] = f2tf(a3); al[3] = __float_as_uint(a3 - __uint_as_float(ah[3]));
                #pragma unroll
                for (int nt = 0; nt < 4; nt++) {
                    mma_tf32(c[mt2][nt], ah, bh[nt][0], bh[nt][1]);
                    mma_tf32(c[mt2][nt], ah, bl[nt][0], bl[nt][1]);
                    mma_tf32(c[mt2][nt], al, bh[nt][0], bh[nt][1]);
                }
            }
        }

        float lgt[4][2];
        #pragma unroll
        for (int nt = 0; nt < 4; nt++) { lgt[nt][0] = 0.f; lgt[nt][1] = 0.f; }

        #pragma unroll
        for (int mt2 = 0; mt2 < 2; mt2++) {
            const int d0 = m0 + 16 * mt2 + g;      // d0 in [7, 511)
            const bool hi_ok = (d0 + 8 < 512);
            #pragma unroll
            for (int nt = 0; nt < 4; nt++) {
                const int t0 = 8 * nt + 2 * tg;
                float* r0 = out_avo + ((size_t)blk * TW + t0) * DD;
                float* r1 = r0 + DD;
                r0[d0] = c[mt2][nt][0];
                r1[d0] = c[mt2][nt][1];
                lgt[nt][0] += c[mt2][nt][0] * w_s[t0 * WSTR + d0];
                lgt[nt][1] += c[mt2][nt][1] * w_s[(t0 + 1) * WSTR + d0];
                if (hi_ok) {
                    r0[d0 + 8] = c[mt2][nt][2];
                    r1[d0 + 8] = c[mt2][nt][3];
                    lgt[nt][0] += c[mt2][nt][2] * w_s[t0 * WSTR + d0 + 8];
                    lgt[nt][1] += c[mt2][nt][3] * w_s[(t0 + 1) * WSTR + d0 + 8];
                }
            }
        }
        // reduce over g (lane = 4g+tg): xor masks 4,8,16
        #pragma unroll
        for (int s = 4; s < 32; s <<= 1)
            #pragma unroll
            for (int nt = 0; nt < 4; nt++) {
                lgt[nt][0] += __shfl_xor_sync(0xffffffffu, lgt[nt][0], s);
                lgt[nt][1] += __shfl_xor_sync(0xffffffffu, lgt[nt][1], s);
            }
        if (g == 0) {
            #pragma unroll
            for (int nt = 0; nt < 4; nt++) {
                lgp[(8 * nt + 2 * tg)     * 16 + wrp] = lgt[nt][0];
                lgp[(8 * nt + 2 * tg + 1) * 16 + wrp] = lgt[nt][1];
            }
        }
    } else {
        // warps 16-17: edge columns d in [0,7), 32 t rows = 224 tasks
        const int base = tid - 512;
        #pragma unroll
        for (int rep = 0; rep < 4; rep++) {
            int task = base + 64 * rep;
            if (task < 224) {
                int t = task / 7, e = task % 7;
                float acc = 0.f;
                #pragma unroll 4
                for (int o = 0; o < TO; o++)
                    acc += att_al[t * ASTR + o] * uo[o * OSTR2 + 1 + e];
                out_avo[((size_t)blk * TW + t) * DD + e] = acc;
                lgp2[task] = acc * w_s[t * WSTR + e];
            }
        }
    }
    __syncthreads();

    if (tid < 32) {
        float s = 0.f;
        #pragma unroll
        for (int k = 0; k < 16; k++) s += lgp[tid * 16 + k];
        #pragma unroll
        for (int e = 0; e < 7; e++)  s += lgp2[tid * 7 + e];
        g_logits[(wb * TW + tid) * BO + ob] = s;
    }
}

// log-softmax over Bo + masked diagonal accumulation, one block per wb
__global__ void cap_loss1(const int* __restrict__ g_mask)
{
    const int wb   = blockIdx.x;
    const int wid  = threadIdx.x >> 5;
    const int lane = threadIdx.x & 31;
    __shared__ float warp_part[8];

    float keepl = 1.f - (float)g_mask[wb * TW + lane];
    float nk = keepl;
    #pragma unroll
    for (int s = 16; s; s >>= 1) nk += __shfl_xor_sync(0xffffffffu, nk, s);

    float acc = 0.f;
    #pragma unroll
    for (int k = 0; k < 4; k++) {
        int t = wid + 8 * k;
        const float* row = g_logits + (wb * TW + t) * BO;
        float v0 = row[lane], v1 = row[lane + 32];
        float m = fmaxf(v0, v1);
        #pragma unroll
        for (int s = 16; s; s >>= 1) m = fmaxf(m, __shfl_xor_sync(0xffffffffu, m, s));
        float e = expf(v0 - m) + expf(v1 - m);
        #pragma unroll
        for (int s = 16; s; s >>= 1) e += __shfl_xor_sync(0xffffffffu, e, s);
        float lse = m + logf(e);
        float dv = (wb < 32) ? __shfl_sync(0xffffffffu, v0, wb)
                             : __shfl_sync(0xffffffffu, v1, wb - 32);
        float kt = 1.f - (float)g_mask[wb * TW + t];
        acc += kt * (dv - lse);
    }
    if (lane == 0) warp_part[wid] = acc;
    __syncthreads();
    if (threadIdx.x == 0) {
        float s = 0.f;
        #pragma unroll
        for (int k = 0; k < 8; k++) s += warp_part[k];
        g_partial[wb] = s / (nk + 1e-6f);
    }
}

__global__ void cap_loss2(float* __restrict__ out)
{
    __shared__ float sh[64];
    sh[threadIdx.x] = g_partial[threadIdx.x];
    __syncthreads();
    if (threadIdx.x == 0) {
        float s = 0.f;
        #pragma unroll
        for (int k = 0; k < 64; k++) s += sh[k];
        out[0] = -s / 64.f;
    }
}

extern "C" void kernel_launch(void* const* d_in, const int* in_sizes, int n_in,
                              void* d_out, int out_size)
{
    const float* g_o    = (const float*)d_in[0];
    const float* g_u    = (const float*)d_in[1];
    const float* g_w    = (const float*)d_in[2];
    const int*   g_mask = (const int*)d_in[3];

    float* out     = (float*)d_out;
    float* out_att = out + 1;
    float* out_avo = out_att + (size_t)BW * BO * TW * TO;

    const size_t SMEM_BYTES = (size_t)SMEM_FLOATS * sizeof(float);
    cudaFuncSetAttribute(cap_main, cudaFuncAttributeMaxDynamicSharedMemorySize,
                         (int)SMEM_BYTES);

    dim3 grid(BO, BW);
    cap_main<<<grid, NTHR, SMEM_BYTES>>>(g_o, g_u, g_w, out_att, out_avo);
    cap_loss1<<<BW, 256>>>(g_mask);
    cap_loss2<<<1, 64>>>(out);
}

// round 12
// speedup vs baseline: 1.4645x; 1.0334x over previous
#include <cuda_runtime.h>
#include <math.h>
#include <stdint.h>

#define BW 64
#define BO 64
#define TW 32
#define TO 36
#define DD 512
#define SCALE 0.044194173824159216f  // 1/sqrt(512)
#define WSTR 516                     // w row stride
#define USTR 516                     // u row stride (phase 2)
#define OSTR2 520                    // o row stride (phase 4), +1 shifted
#define ASTR 44                      // att hi/lo row stride
#define NTHR 576

// smem layout (float offsets)
#define OFF_W     0          // 32*516 = 16512
#define OFF_UO    16512      // max(40*516, 40*520) = 20800
#define OFF_P2    37312      // 8*1280 = 10240
#define OFF_ATTC  47552      // 1168
#define OFF_ATTHI 48720      // 32*44 = 1408 (tf32-rounded att)
#define OFF_ATTLO 50128      // 32*44 = 1408 (fp32 residual)
#define OFF_LGP   51536      // 32*16 = 512
#define OFF_LGP2  52048      // 32*7 = 224
#define SMEM_FLOATS 52272    // 209088 bytes

__device__ float g_logits[BW * TW * BO];   // [wb][t][ob]
__device__ float g_partial[BW];

__device__ __forceinline__ uint32_t f2tf(float x) {
    uint32_t r; asm("cvt.rna.tf32.f32 %0, %1;" : "=r"(r) : "f"(x)); return r;
}
__device__ __forceinline__ void mma_tf32(float* c, const uint32_t* a,
                                         uint32_t b0, uint32_t b1) {
    asm("mma.sync.aligned.m16n8k8.row.col.f32.tf32.tf32.f32 "
        "{%0,%1,%2,%3}, {%4,%5,%6,%7}, {%8,%9}, {%0,%1,%2,%3};"
        : "+f"(c[0]), "+f"(c[1]), "+f"(c[2]), "+f"(c[3])
        : "r"(a[0]), "r"(a[1]), "r"(a[2]), "r"(a[3]), "r"(b0), "r"(b1));
}

extern __shared__ float smem[];

__global__ __launch_bounds__(NTHR, 1)
void cap_main(const float* __restrict__ g_o,
              const float* __restrict__ g_u,
              const float* __restrict__ g_w,
              float* __restrict__ out_att,   // = d_out + 1
              float* __restrict__ out_avo)   // = d_out + 1 + 64*64*32*36
{
    const int ob  = blockIdx.x;
    const int wb  = blockIdx.y;
    const int blk = wb * BO + ob;
    const int tid = threadIdx.x;

    float*  w_s    = smem + OFF_W;
    float*  uo     = smem + OFF_UO;     // u (str 516) then o (str 520, +1 shift)
    float*  p2     = smem + OFF_P2;
    float*  att_cs = smem + OFF_ATTC;
    float*  att_hi = smem + OFF_ATTHI;
    float*  att_lo = smem + OFF_ATTLO;
    float*  lgp    = smem + OFF_LGP;
    float*  lgp2   = smem + OFF_LGP2;

    const int wrp  = tid >> 5;
    const int lane = tid & 31;
    const int g    = lane >> 2;      // mma groupID
    const int tg   = lane & 3;       // mma threadID in group

    // ---------- phase 1: load w (32x512) and u (36x512); zero pads ----------
    for (int idx = tid; idx < TW * 128; idx += NTHR) {
        int t = idx >> 7, c = idx & 127;
        float4 v = reinterpret_cast<const float4*>(g_w)[((size_t)wb * TW + t) * 128 + c];
        *reinterpret_cast<float4*>(&w_s[t * WSTR + 4 * c]) = v;
    }
    if (tid < 128) {                               // w pad cols 512-515 zero
        int t = tid >> 2, j = tid & 3;
        w_s[t * WSTR + 512 + j] = 0.f;
    }
    for (int idx = tid; idx < TO * 128; idx += NTHR) {
        int o = idx >> 7, c = idx & 127;
        float4 v = reinterpret_cast<const float4*>(g_u)[((size_t)ob * TO + o) * 128 + c];
        *reinterpret_cast<float4*>(&uo[o * USTR + 4 * c]) = v;
    }
    for (int idx = tid; idx < 4 * USTR; idx += NTHR)
        uo[TO * USTR + idx] = 0.f;                 // u rows 36-39 zero
    if (tid < 512) {                               // att hi/lo k-pad cols 36-43
        int arr = tid >> 8, r = (tid & 255) >> 3, j = tid & 7;
        (arr ? att_lo : att_hi)[r * ASTR + 36 + j] = 0.f;
    }
    __syncthreads();

    // ---------- phase 2: scores via tf32 mma (3-term split) -----------------
    if (wrp < 16) {
        const int mt = wrp & 1;
        const int ks = wrp >> 1;

        float c[5][4];
        #pragma unroll
        for (int nt = 0; nt < 5; nt++)
            #pragma unroll
            for (int q = 0; q < 4; q++) c[nt][q] = 0.f;

        const float* wrow0 = w_s + (16 * mt + g) * WSTR;
        const float* wrow1 = wrow0 + 8 * WSTR;

        #pragma unroll 2
        for (int j = 0; j < 8; j++) {
            const int k0 = (ks * 8 + j) * 8;
            float a0 = wrow0[k0 + tg];
            float a1 = wrow1[k0 + tg];
            float a2 = wrow0[k0 + tg + 4];
            float a3 = wrow1[k0 + tg + 4];
            uint32_t ah[4], al[4];
            ah[0] = f2tf(a0); al[0] = __float_as_uint(a0 - __uint_as_float(ah[0]));
            ah[1] = f2tf(a1); al[1] = __float_as_uint(a1 - __uint_as_float(ah[1]));
            ah[2] = f2tf(a2); al[2] = __float_as_uint(a2 - __uint_as_float(ah[2]));
            ah[3] = f2tf(a3); al[3] = __float_as_uint(a3 - __uint_as_float(ah[3]));
            #pragma unroll
            for (int nt = 0; nt < 5; nt++) {
                const float* ur = uo + (8 * nt + g) * USTR + k0;
                float b0 = ur[tg];
                float b1 = ur[tg + 4];
                uint32_t bh0 = f2tf(b0);
                uint32_t bh1 = f2tf(b1);
                uint32_t bl0 = __float_as_uint(b0 - __uint_as_float(bh0));
                uint32_t bl1 = __float_as_uint(b1 - __uint_as_float(bh1));
                mma_tf32(c[nt], ah, bh0, bh1);
                mma_tf32(c[nt], ah, bl0, bl1);
                mma_tf32(c[nt], al, bh0, bh1);
            }
        }
        float* pp = p2 + ks * 1280 + (16 * mt) * 40;
        #pragma unroll
        for (int nt = 0; nt < 5; nt++) {
            int col = 8 * nt + 2 * tg;
            *reinterpret_cast<float2*>(&pp[g * 40 + col])       = make_float2(c[nt][0], c[nt][1]);
            *reinterpret_cast<float2*>(&pp[(g + 8) * 40 + col]) = make_float2(c[nt][2], c[nt][3]);
        }
    }
    __syncthreads();

    // ---------- phase 4a (early): o tile load, overlaps softmax -------------
    for (int task = tid; task < TO * 127; task += NTHR) {
        int o = task / 127, k = task % 127;
        const float* gr = g_o + ((size_t)ob * TO + o) * 512;
        float4 A  = *reinterpret_cast<const float4*>(&gr[4 * k]);
        float4 Bv = *reinterpret_cast<const float4*>(&gr[4 * k + 4]);
        *reinterpret_cast<float4*>(&uo[o * OSTR2 + 4 + 4 * k]) =
            make_float4(A.w, Bv.x, Bv.y, Bv.z);
    }
    if (tid < 144) {
        int o = tid / 4, e = tid % 4;
        const float* gr = g_o + ((size_t)ob * TO + o) * 512;
        if (e < 3) uo[o * OSTR2 + 1 + e] = gr[e];
        else       uo[o * OSTR2 + 512]   = gr[511];
    }
    for (int idx = tid; idx < 4 * OSTR2; idx += NTHR)
        uo[TO * OSTR2 + idx] = 0.f;                // o rows 36-39 full zero
    for (int idx = tid; idx < TO * 7; idx += NTHR) {
        int o = idx / 7, cc = idx % 7;             // o pad cols 513-519 zero
        uo[o * OSTR2 + 513 + cc] = 0.f;
    }

    // ---------- phase 3: warp-level softmax (no internal barriers) ----------
    // 16 warps, half-warp per t row: row = 2*wrp + (lane>>4), cols li,li+16,li+32
    if (wrp < 16) {
        const int row = 2 * wrp + (lane >> 4);
        const int li  = lane & 15;
        float s0 = 0.f, s1 = 0.f, s2 = 0.f;
        const float* pr = p2 + row * 40;
        #pragma unroll
        for (int ks = 0; ks < 8; ks++) {
            const float* q = pr + ks * 1280;
            s0 += q[li];
            s1 += q[li + 16];
            if (li < 4) s2 += q[li + 32];
        }
        s0 *= SCALE; s1 *= SCALE; s2 *= SCALE;
        float m = fmaxf(s0, s1);
        if (li < 4) m = fmaxf(m, s2);
        #pragma unroll
        for (int k = 1; k < 16; k <<= 1)
            m = fmaxf(m, __shfl_xor_sync(0xffffffffu, m, k));
        float e0 = expf(s0 - m), e1 = expf(s1 - m);
        float e2 = (li < 4) ? expf(s2 - m) : 0.f;
        float ss = e0 + e1 + e2;
        #pragma unroll
        for (int k = 1; k < 16; k <<= 1)
            ss += __shfl_xor_sync(0xffffffffu, ss, k);
        float inv = 1.f / ss;
        float a0 = e0 * inv, a1 = e1 * inv, a2 = e2 * inv;

        att_cs[1 + row * TO + li]      = a0;
        att_cs[1 + row * TO + li + 16] = a1;
        float h0 = __uint_as_float(f2tf(a0));
        float h1 = __uint_as_float(f2tf(a1));
        att_hi[row * ASTR + li]      = h0;  att_lo[row * ASTR + li]      = a0 - h0;
        att_hi[row * ASTR + li + 16] = h1;  att_lo[row * ASTR + li + 16] = a1 - h1;
        if (li < 4) {
            att_cs[1 + row * TO + li + 32] = a2;
            float h2 = __uint_as_float(f2tf(a2));
            att_hi[row * ASTR + li + 32] = h2;
            att_lo[row * ASTR + li + 32] = a2 - h2;
        }
    }
    __syncthreads();

    // ---------- phase 4b (warps 0-15) ∥ att store + edges (warps 16-17) -----
    if (wrp < 16) {
        const int m0 = 7 + 32 * wrp;               // warp d base

        float c[2][4][4];
        #pragma unroll
        for (int mt2 = 0; mt2 < 2; mt2++)
            #pragma unroll
            for (int nt = 0; nt < 4; nt++)
                #pragma unroll
                for (int q = 0; q < 4; q++) c[mt2][nt][q] = 0.f;

        #pragma unroll
        for (int kk = 0; kk < 5; kk++) {
            const int k0 = 8 * kk;
            uint32_t bh[4][2], bl[4][2];
            #pragma unroll
            for (int nt = 0; nt < 4; nt++) {
                const int rb = (8 * nt + g) * ASTR + k0 + tg;
                bh[nt][0] = __float_as_uint(att_hi[rb]);
                bh[nt][1] = __float_as_uint(att_hi[rb + 4]);
                bl[nt][0] = __float_as_uint(att_lo[rb]);
                bl[nt][1] = __float_as_uint(att_lo[rb + 4]);
            }
            #pragma unroll
            for (int mt2 = 0; mt2 < 2; mt2++) {
                const int mb = m0 + 16 * mt2;
                const float* ab_ = uo + (k0 + tg) * OSTR2 + 1 + mb + g;
                float a0 = ab_[0];
                float a1 = ab_[8];
                float a2 = ab_[4 * OSTR2];
                float a3 = ab_[4 * OSTR2 + 8];
                uint32_t ah[4], al[4];
                ah[0] = f2tf(a0); al[0] = __float_as_uint(a0 - __uint_as_float(ah[0]));
                ah[1] = f2tf(a1); al[1] = __float_as_uint(a1 - __uint_as_float(ah[1]));
                ah[2] = f2tf(a2); al[2] = __float_as_uint(a2 - __uint_as_float(ah[2]));
                ah[3] = f2tf(a3); al[3] = __float_as_uint(a3 - __uint_as_float(ah[3]));
                #pragma unroll
                for (int nt = 0; nt < 4; nt++) {
                    mma_tf32(c[mt2][nt], ah, bh[nt][0], bh[nt][1]);
                    mma_tf32(c[mt2][nt], ah, bl[nt][0], bl[nt][1]);
                    mma_tf32(c[mt2][nt], al, bh[nt][0], bh[nt][1]);
                }
            }
        }

        float lgt[4][2];
        #pragma unroll
        for (int nt = 0; nt < 4; nt++) { lgt[nt][0] = 0.f; lgt[nt][1] = 0.f; }

        #pragma unroll
        for (int mt2 = 0; mt2 < 2; mt2++) {
            const int d0 = m0 + 16 * mt2 + g;      // d0 in [7, 511)
            const bool hi_ok = (d0 + 8 < 512);
            #pragma unroll
            for (int nt = 0; nt < 4; nt++) {
                const int t0 = 8 * nt + 2 * tg;
                float* r0 = out_avo + ((size_t)blk * TW + t0) * DD;
                float* r1 = r0 + DD;
                r0[d0] = c[mt2][nt][0];
                r1[d0] = c[mt2][nt][1];
                lgt[nt][0] += c[mt2][nt][0] * w_s[t0 * WSTR + d0];
                lgt[nt][1] += c[mt2][nt][1] * w_s[(t0 + 1) * WSTR + d0];
                if (hi_ok) {
                    r0[d0 + 8] = c[mt2][nt][2];
                    r1[d0 + 8] = c[mt2][nt][3];
                    lgt[nt][0] += c[mt2][nt][2] * w_s[t0 * WSTR + d0 + 8];
                    lgt[nt][1] += c[mt2][nt][3] * w_s[(t0 + 1) * WSTR + d0 + 8];
                }
            }
        }
        // reduce over g (lane = 4g+tg): xor masks 4,8,16
        #pragma unroll
        for (int s = 4; s < 32; s <<= 1)
            #pragma unroll
            for (int nt = 0; nt < 4; nt++) {
                lgt[nt][0] += __shfl_xor_sync(0xffffffffu, lgt[nt][0], s);
                lgt[nt][1] += __shfl_xor_sync(0xffffffffu, lgt[nt][1], s);
            }
        if (g == 0) {
            #pragma unroll
            for (int nt = 0; nt < 4; nt++) {
                lgp[(8 * nt + 2 * tg)     * 16 + wrp] = lgt[nt][0];
                lgp[(8 * nt + 2 * tg + 1) * 16 + wrp] = lgt[nt][1];
            }
        }
    } else {
        // warps 16-17: att global store + edge columns d in [0,7)
        const int base = tid - 512;
        {
            const size_t ab = (size_t)blk * (TW * TO);
            for (int j = base; j < 287; j += 64) {
                float4 v = *reinterpret_cast<const float4*>(&att_cs[4 + 4 * j]);
                *reinterpret_cast<float4*>(&out_att[ab + 3 + 4 * j]) = v;
            }
            if (base == 63) {
                out_att[ab + 0]    = att_cs[1];
                out_att[ab + 1]    = att_cs[2];
                out_att[ab + 2]    = att_cs[3];
                out_att[ab + 1151] = att_cs[1152];
            }
        }
        #pragma unroll
        for (int rep = 0; rep < 4; rep++) {
            int task = base + 64 * rep;
            if (task < 224) {
                int t = task / 7, e = task % 7;
                float acc = 0.f;
                #pragma unroll 4
                for (int o = 0; o < TO; o++)
                    acc += att_cs[1 + t * TO + o] * uo[o * OSTR2 + 1 + e];
                out_avo[((size_t)blk * TW + t) * DD + e] = acc;
                lgp2[task] = acc * w_s[t * WSTR + e];
            }
        }
    }
    __syncthreads();

    if (tid < 32) {
        float s = 0.f;
        #pragma unroll
        for (int k = 0; k < 16; k++) s += lgp[tid * 16 + k];
        #pragma unroll
        for (int e = 0; e < 7; e++)  s += lgp2[tid * 7 + e];
        g_logits[(wb * TW + tid) * BO + ob] = s;
    }
}

// log-softmax over Bo + masked diagonal accumulation, one block per wb
__global__ void cap_loss1(const int* __restrict__ g_mask)
{
    const int wb   = blockIdx.x;
    const int wid  = threadIdx.x >> 5;
    const int lane = threadIdx.x & 31;
    __shared__ float warp_part[8];

    float keepl = 1.f - (float)g_mask[wb * TW + lane];
    float nk = keepl;
    #pragma unroll
    for (int s = 16; s; s >>= 1) nk += __shfl_xor_sync(0xffffffffu, nk, s);

    float acc = 0.f;
    #pragma unroll
    for (int k = 0; k < 4; k++) {
        int t = wid + 8 * k;
        const float* row = g_logits + (wb * TW + t) * BO;
        float v0 = row[lane], v1 = row[lane + 32];
        float m = fmaxf(v0, v1);
        #pragma unroll
        for (int s = 16; s; s >>= 1) m = fmaxf(m, __shfl_xor_sync(0xffffffffu, m, s));
        float e = expf(v0 - m) + expf(v1 - m);
        #pragma unroll
        for (int s = 16; s; s >>= 1) e += __shfl_xor_sync(0xffffffffu, e, s);
        float lse = m + logf(e);
        float dv = (wb < 32) ? __shfl_sync(0xffffffffu, v0, wb)
                             : __shfl_sync(0xffffffffu, v1, wb - 32);
        float kt = 1.f - (float)g_mask[wb * TW + t];
        acc += kt * (dv - lse);
    }
    if (lane == 0) warp_part[wid] = acc;
    __syncthreads();
    if (threadIdx.x == 0) {
        float s = 0.f;
        #pragma unroll
        for (int k = 0; k < 8; k++) s += warp_part[k];
        g_partial[wb] = s / (nk + 1e-6f);
    }
}

__global__ void cap_loss2(float* __restrict__ out)
{
    __shared__ float sh[64];
    sh[threadIdx.x] = g_partial[threadIdx.x];
    __syncthreads();
    if (threadIdx.x == 0) {
        float s = 0.f;
        #pragma unroll
        for (int k = 0; k < 64; k++) s += sh[k];
        out[0] = -s / 64.f;
    }
}

extern "C" void kernel_launch(void* const* d_in, const int* in_sizes, int n_in,
                              void* d_out, int out_size)
{
    const float* g_o    = (const float*)d_in[0];
    const float* g_u    = (const float*)d_in[1];
    const float* g_w    = (const float*)d_in[2];
    const int*   g_mask = (const int*)d_in[3];

    float* out     = (float*)d_out;
    float* out_att = out + 1;
    float* out_avo = out_att + (size_t)BW * BO * TW * TO;

    const size_t SMEM_BYTES = (size_t)SMEM_FLOATS * sizeof(float);
    cudaFuncSetAttribute(cap_main, cudaFuncAttributeMaxDynamicSharedMemorySize,
                         (int)SMEM_BYTES);

    dim3 grid(BO, BW);
    cap_main<<<grid, NTHR, SMEM_BYTES>>>(g_o, g_u, g_w, out_att, out_avo);
    cap_loss1<<<BW, 256>>>(g_mask);
    cap_loss2<<<1, 64>>>(out);
}

// round 13
// speedup vs baseline: 1.6155x; 1.1031x over previous
#include <cuda_runtime.h>
#include <math.h>
#include <stdint.h>

#define BW 64
#define BO 64
#define TW 32
#define TO 36
#define DD 512
#define SCALE 0.044194173824159216f  // 1/sqrt(512)
#define NTHR 576

#define WHS 260     // w hi/lo word stride (words of bf16x2), 260%32=4
#define UHS 260     // u hi/lo word stride
#define OPS 520     // o-pair word stride, 520%32=8
#define ATS 28      // att word stride, 28%32=28

// smem layout (4-byte word offsets)
#define OFF_WH   0          // 32*260 = 8320
#define OFF_WL   8320       // 8320
#define OFF_UO   16640      // region 24960: u_hi(10400)+u_lo(10400) / o_hi(12480)+o_lo(12480)
#define OFF_P2   41600      // 8*1280 = 10240
#define OFF_ATTC 51840      // 1168
#define OFF_ATH  53008      // 32*28 = 896
#define OFF_ATL  53904      // 896
#define OFF_LGP  54800      // 512
#define OFF_LGP2 55312      // 224
#define SMEM_FLOATS 55536   // 222144 bytes

__device__ float g_logits[BW * TW * BO];   // [wb][t][ob]
__device__ float g_partial[BW];

// split x,y into bf16 hi word {lo=bf16(x), hi=bf16(y)} + bf16 residual word
__device__ __forceinline__ uint32_t packsplit(float x, float y, uint32_t &lo) {
    uint32_t h;
    asm("cvt.rn.satfinite.bf16x2.f32 %0, %1, %2;" : "=r"(h) : "f"(y), "f"(x));
    float hx = __uint_as_float(h << 16);
    float hy = __uint_as_float(h & 0xffff0000u);
    float rx = x - hx, ry = y - hy;
    asm("cvt.rn.satfinite.bf16x2.f32 %0, %1, %2;" : "=r"(lo) : "f"(ry), "f"(rx));
    return h;
}
__device__ __forceinline__ float bfhalf(uint32_t w, int odd) {
    return __uint_as_float(odd ? (w & 0xffff0000u) : (w << 16));
}
__device__ __forceinline__ void mma_bf16(float* c, const uint32_t* a,
                                         uint32_t b0, uint32_t b1) {
    asm("mma.sync.aligned.m16n8k16.row.col.f32.bf16.bf16.f32 "
        "{%0,%1,%2,%3}, {%4,%5,%6,%7}, {%8,%9}, {%0,%1,%2,%3};"
        : "+f"(c[0]), "+f"(c[1]), "+f"(c[2]), "+f"(c[3])
        : "r"(a[0]), "r"(a[1]), "r"(a[2]), "r"(a[3]), "r"(b0), "r"(b1));
}

extern __shared__ float smem[];

__global__ __launch_bounds__(NTHR, 1)
void cap_main(const float* __restrict__ g_o,
              const float* __restrict__ g_u,
              const float* __restrict__ g_w,
              float* __restrict__ out_att,   // = d_out + 1
              float* __restrict__ out_avo)   // = d_out + 1 + 64*64*32*36
{
    const int ob  = blockIdx.x;
    const int wb  = blockIdx.y;
    const int blk = wb * BO + ob;
    const int tid = threadIdx.x;

    uint32_t* wh  = (uint32_t*)(smem + OFF_WH);
    uint32_t* wl  = (uint32_t*)(smem + OFF_WL);
    uint32_t* uh  = (uint32_t*)(smem + OFF_UO);           // phase 2
    uint32_t* ul  = uh + 10400;
    uint32_t* ohw = (uint32_t*)(smem + OFF_UO);           // phase 4 (reuse)
    uint32_t* olw = ohw + 12480;
    float*    p2     = smem + OFF_P2;
    float*    att_cs = smem + OFF_ATTC;
    uint32_t* ath    = (uint32_t*)(smem + OFF_ATH);
    uint32_t* atl    = (uint32_t*)(smem + OFF_ATL);
    float*    lgp    = smem + OFF_LGP;
    float*    lgp2   = smem + OFF_LGP2;

    const int wrp  = tid >> 5;
    const int lane = tid & 31;
    const int g    = lane >> 2;      // mma groupID
    const int tg   = lane & 3;       // mma threadID in group

    // ---------- phase 1: load + bf16-split w (32x512) and u (36x512) --------
    for (int idx = tid; idx < TW * 128; idx += NTHR) {
        int t = idx >> 7, c = idx & 127;
        float4 v = reinterpret_cast<const float4*>(g_w)[((size_t)wb * TW + t) * 128 + c];
        uint32_t l0, l1;
        uint32_t h0 = packsplit(v.x, v.y, l0);
        uint32_t h1 = packsplit(v.z, v.w, l1);
        *reinterpret_cast<uint2*>(&wh[t * WHS + 2 * c]) = make_uint2(h0, h1);
        *reinterpret_cast<uint2*>(&wl[t * WHS + 2 * c]) = make_uint2(l0, l1);
    }
    for (int idx = tid; idx < TO * 128; idx += NTHR) {
        int o = idx >> 7, c = idx & 127;
        float4 v = reinterpret_cast<const float4*>(g_u)[((size_t)ob * TO + o) * 128 + c];
        uint32_t l0, l1;
        uint32_t h0 = packsplit(v.x, v.y, l0);
        uint32_t h1 = packsplit(v.z, v.w, l1);
        *reinterpret_cast<uint2*>(&uh[o * UHS + 2 * c]) = make_uint2(h0, h1);
        *reinterpret_cast<uint2*>(&ul[o * UHS + 2 * c]) = make_uint2(l0, l1);
    }
    for (int idx = tid; idx < 4 * UHS; idx += NTHR) {   // u n-pad rows 36-39
        uh[36 * UHS + idx] = 0u;
        ul[36 * UHS + idx] = 0u;
    }
    if (tid < 192) {                                     // att k-pad words 18-23
        int r = tid / 6, j = tid % 6;
        ath[r * ATS + 18 + j] = 0u;
        atl[r * ATS + 18 + j] = 0u;
    }
    __syncthreads();

    // ---------- phase 2: scores via bf16 mma (3-term, k16) ------------------
    if (wrp < 16) {
        const int mt = wrp & 1;
        const int ks = wrp >> 1;

        float c[5][4];
        #pragma unroll
        for (int nt = 0; nt < 5; nt++)
            #pragma unroll
            for (int q = 0; q < 4; q++) c[nt][q] = 0.f;

        const uint32_t* whr0 = wh + (16 * mt + g) * WHS;
        const uint32_t* whr1 = whr0 + 8 * WHS;
        const uint32_t* wlr0 = wl + (16 * mt + g) * WHS;
        const uint32_t* wlr1 = wlr0 + 8 * WHS;

        #pragma unroll
        for (int j = 0; j < 4; j++) {
            const int kw = ks * 32 + j * 8;
            uint32_t ah[4], al[4];
            ah[0] = whr0[kw + tg];     ah[1] = whr1[kw + tg];
            ah[2] = whr0[kw + tg + 4]; ah[3] = whr1[kw + tg + 4];
            al[0] = wlr0[kw + tg];     al[1] = wlr1[kw + tg];
            al[2] = wlr0[kw + tg + 4]; al[3] = wlr1[kw + tg + 4];
            #pragma unroll
            for (int nt = 0; nt < 5; nt++) {
                const uint32_t* ur = uh + (8 * nt + g) * UHS + kw;
                const uint32_t* lr = ul + (8 * nt + g) * UHS + kw;
                uint32_t bh0 = ur[tg], bh1 = ur[tg + 4];
                uint32_t bl0 = lr[tg], bl1 = lr[tg + 4];
                mma_bf16(c[nt], ah, bh0, bh1);
                mma_bf16(c[nt], ah, bl0, bl1);
                mma_bf16(c[nt], al, bh0, bh1);
            }
        }
        float* pp = p2 + ks * 1280 + (16 * mt) * 40;
        #pragma unroll
        for (int nt = 0; nt < 5; nt++) {
            int col = 8 * nt + 2 * tg;
            *reinterpret_cast<float2*>(&pp[g * 40 + col])       = make_float2(c[nt][0], c[nt][1]);
            *reinterpret_cast<float2*>(&pp[(g + 8) * 40 + col]) = make_float2(c[nt][2], c[nt][3]);
        }
    }
    __syncthreads();

    // ---------- phase 4a (early): o load + split + o-pair pack --------------
    for (int task = tid; task < 18 * 128; task += NTHR) {
        int op = task >> 7, d4 = task & 127;
        const float* rA = g_o + ((size_t)ob * TO + 2 * op) * 512 + 4 * d4;
        float4 A = *reinterpret_cast<const float4*>(rA);
        float4 B = *reinterpret_cast<const float4*>(rA + 512);
        uint32_t h[4], l[4];
        h[0] = packsplit(A.x, B.x, l[0]);
        h[1] = packsplit(A.y, B.y, l[1]);
        h[2] = packsplit(A.z, B.z, l[2]);
        h[3] = packsplit(A.w, B.w, l[3]);
        *reinterpret_cast<uint4*>(&ohw[op * OPS + 4 * d4]) = make_uint4(h[0], h[1], h[2], h[3]);
        *reinterpret_cast<uint4*>(&olw[op * OPS + 4 * d4]) = make_uint4(l[0], l[1], l[2], l[3]);
    }
    for (int idx = tid; idx < 6 * OPS; idx += NTHR) {    // o k-pad rows 18-23
        ohw[18 * OPS + idx] = 0u;
        olw[18 * OPS + idx] = 0u;
    }
    if (tid < 144) {                                     // o d-pad cols 512-519
        int op = tid >> 3, j = tid & 7;
        ohw[op * OPS + 512 + j] = 0u;
        olw[op * OPS + 512 + j] = 0u;
    }

    // ---------- phase 3: warp-level softmax (pair lanes, no barriers) -------
    if (wrp < 16) {
        const int row = 2 * wrp + (lane >> 4);
        const int li  = lane & 15;
        const float* pr = p2 + row * 40;
        float s0 = 0.f, s1 = 0.f, s2 = 0.f, s3 = 0.f;
        #pragma unroll
        for (int ks = 0; ks < 8; ks++) {
            float2 v = *reinterpret_cast<const float2*>(&pr[ks * 1280 + 2 * li]);
            s0 += v.x; s1 += v.y;
            if (li < 2) {
                float2 v2 = *reinterpret_cast<const float2*>(&pr[ks * 1280 + 32 + 2 * li]);
                s2 += v2.x; s3 += v2.y;
            }
        }
        s0 *= SCALE; s1 *= SCALE; s2 *= SCALE; s3 *= SCALE;
        float m = fmaxf(s0, s1);
        if (li < 2) m = fmaxf(m, fmaxf(s2, s3));
        #pragma unroll
        for (int k = 1; k < 16; k <<= 1)
            m = fmaxf(m, __shfl_xor_sync(0xffffffffu, m, k));
        float e0 = expf(s0 - m), e1 = expf(s1 - m);
        float e2 = (li < 2) ? expf(s2 - m) : 0.f;
        float e3 = (li < 2) ? expf(s3 - m) : 0.f;
        float ss = e0 + e1 + e2 + e3;
        #pragma unroll
        for (int k = 1; k < 16; k <<= 1)
            ss += __shfl_xor_sync(0xffffffffu, ss, k);
        float inv = 1.f / ss;
        float a0 = e0 * inv, a1 = e1 * inv;

        att_cs[1 + row * TO + 2 * li]     = a0;
        att_cs[1 + row * TO + 2 * li + 1] = a1;
        uint32_t lo;
        uint32_t h = packsplit(a0, a1, lo);
        ath[row * ATS + li] = h;
        atl[row * ATS + li] = lo;
        if (li < 2) {
            float a2 = e2 * inv, a3 = e3 * inv;
            att_cs[1 + row * TO + 32 + 2 * li]     = a2;
            att_cs[1 + row * TO + 32 + 2 * li + 1] = a3;
            uint32_t lo2;
            uint32_t h2 = packsplit(a2, a3, lo2);
            ath[row * ATS + 16 + li] = h2;
            atl[row * ATS + 16 + li] = lo2;
        }
    }
    __syncthreads();

    // ---------- phase 4b (warps 0-15) ∥ att store + edges (warps 16-17) -----
    if (wrp < 16) {
        const int m0 = 7 + 32 * wrp;               // warp d base

        float c[2][4][4];
        #pragma unroll
        for (int mt2 = 0; mt2 < 2; mt2++)
            #pragma unroll
            for (int nt = 0; nt < 4; nt++)
                #pragma unroll
                for (int q = 0; q < 4; q++) c[mt2][nt][q] = 0.f;

        #pragma unroll
        for (int kk = 0; kk < 3; kk++) {
            uint32_t bh[4][2], bl[4][2];
            #pragma unroll
            for (int nt = 0; nt < 4; nt++) {
                const int rb = (8 * nt + g) * ATS + 8 * kk + tg;
                bh[nt][0] = ath[rb]; bh[nt][1] = ath[rb + 4];
                bl[nt][0] = atl[rb]; bl[nt][1] = atl[rb + 4];
            }
            #pragma unroll
            for (int mt2 = 0; mt2 < 2; mt2++) {
                const int mb = m0 + 16 * mt2;
                const int base = (8 * kk + tg) * OPS + mb + g;
                uint32_t ah[4], al[4];
                ah[0] = ohw[base];           ah[1] = ohw[base + 8];
                ah[2] = ohw[base + 4 * OPS]; ah[3] = ohw[base + 4 * OPS + 8];
                al[0] = olw[base];           al[1] = olw[base + 8];
                al[2] = olw[base + 4 * OPS]; al[3] = olw[base + 4 * OPS + 8];
                #pragma unroll
                for (int nt = 0; nt < 4; nt++) {
                    mma_bf16(c[mt2][nt], ah, bh[nt][0], bh[nt][1]);
                    mma_bf16(c[mt2][nt], ah, bl[nt][0], bl[nt][1]);
                    mma_bf16(c[mt2][nt], al, bh[nt][0], bh[nt][1]);
                }
            }
        }

        float lgt[4][2];
        #pragma unroll
        for (int nt = 0; nt < 4; nt++) { lgt[nt][0] = 0.f; lgt[nt][1] = 0.f; }

        #pragma unroll
        for (int mt2 = 0; mt2 < 2; mt2++) {
            const int d0 = m0 + 16 * mt2 + g;      // d0 in [7, 511)
            const bool hi_ok = (d0 + 8 < 512);
            const int dw = d0 >> 1;
            const int odd = d0 & 1;
            #pragma unroll
            for (int nt = 0; nt < 4; nt++) {
                const int t0 = 8 * nt + 2 * tg;
                float* r0 = out_avo + ((size_t)blk * TW + t0) * DD;
                float* r1 = r0 + DD;
                r0[d0] = c[mt2][nt][0];
                r1[d0] = c[mt2][nt][1];
                float w00 = bfhalf(wh[t0 * WHS + dw], odd)       + bfhalf(wl[t0 * WHS + dw], odd);
                float w10 = bfhalf(wh[(t0 + 1) * WHS + dw], odd) + bfhalf(wl[(t0 + 1) * WHS + dw], odd);
                lgt[nt][0] += c[mt2][nt][0] * w00;
                lgt[nt][1] += c[mt2][nt][1] * w10;
                if (hi_ok) {
                    r0[d0 + 8] = c[mt2][nt][2];
                    r1[d0 + 8] = c[mt2][nt][3];
                    float w01 = bfhalf(wh[t0 * WHS + dw + 4], odd)       + bfhalf(wl[t0 * WHS + dw + 4], odd);
                    float w11 = bfhalf(wh[(t0 + 1) * WHS + dw + 4], odd) + bfhalf(wl[(t0 + 1) * WHS + dw + 4], odd);
                    lgt[nt][0] += c[mt2][nt][2] * w01;
                    lgt[nt][1] += c[mt2][nt][3] * w11;
                }
            }
        }
        // reduce over g (lane = 4g+tg): xor masks 4,8,16
        #pragma unroll
        for (int s = 4; s < 32; s <<= 1)
            #pragma unroll
            for (int nt = 0; nt < 4; nt++) {
                lgt[nt][0] += __shfl_xor_sync(0xffffffffu, lgt[nt][0], s);
                lgt[nt][1] += __shfl_xor_sync(0xffffffffu, lgt[nt][1], s);
            }
        if (g == 0) {
            #pragma unroll
            for (int nt = 0; nt < 4; nt++) {
                lgp[(8 * nt + 2 * tg)     * 16 + wrp] = lgt[nt][0];
                lgp[(8 * nt + 2 * tg + 1) * 16 + wrp] = lgt[nt][1];
            }
        }
    } else {
        // warps 16-17: att global store + edge columns d in [0,7)
        const int base = tid - 512;
        {
            const size_t ab = (size_t)blk * (TW * TO);
            for (int j = base; j < 287; j += 64) {
                float4 v = *reinterpret_cast<const float4*>(&att_cs[4 + 4 * j]);
                *reinterpret_cast<float4*>(&out_att[ab + 3 + 4 * j]) = v;
            }
            if (base == 63) {
                out_att[ab + 0]    = att_cs[1];
                out_att[ab + 1]    = att_cs[2];
                out_att[ab + 2]    = att_cs[3];
                out_att[ab + 1151] = att_cs[1152];
            }
        }
        #pragma unroll
        for (int rep = 0; rep < 4; rep++) {
            int task = base + 64 * rep;
            if (task < 224) {
                int t = task / 7, e = task % 7;
                float acc = 0.f;
                #pragma unroll 4
                for (int o = 0; o < TO; o++) {
                    int op = o >> 1, odd = o & 1;
                    float ov = bfhalf(ohw[op * OPS + e], odd) + bfhalf(olw[op * OPS + e], odd);
                    acc += att_cs[1 + t * TO + o] * ov;
                }
                out_avo[((size_t)blk * TW + t) * DD + e] = acc;
                int dw = e >> 1, odd = e & 1;
                float wv = bfhalf(wh[t * WHS + dw], odd) + bfhalf(wl[t * WHS + dw], odd);
                lgp2[task] = acc * wv;
            }
        }
    }
    __syncthreads();

    if (tid < 32) {
        float s = 0.f;
        #pragma unroll
        for (int k = 0; k < 16; k++) s += lgp[tid * 16 + k];
        #pragma unroll
        for (int e = 0; e < 7; e++)  s += lgp2[tid * 7 + e];
        g_logits[(wb * TW + tid) * BO + ob] = s;
    }
}

// log-softmax over Bo + masked diagonal accumulation, one block per wb
__global__ void cap_loss1(const int* __restrict__ g_mask)
{
    const int wb   = blockIdx.x;
    const int wid  = threadIdx.x >> 5;
    const int lane = threadIdx.x & 31;
    __shared__ float warp_part[8];

    float keepl = 1.f - (float)g_mask[wb * TW + lane];
    float nk = keepl;
    #pragma unroll
    for (int s = 16; s; s >>= 1) nk += __shfl_xor_sync(0xffffffffu, nk, s);

    float acc = 0.f;
    #pragma unroll
    for (int k = 0; k < 4; k++) {
        int t = wid + 8 * k;
        const float* row = g_logits + (wb * TW + t) * BO;
        float v0 = row[lane], v1 = row[lane + 32];
        float m = fmaxf(v0, v1);
        #pragma unroll
        for (int s = 16; s; s >>= 1) m = fmaxf(m, __shfl_xor_sync(0xffffffffu, m, s));
        float e = expf(v0 - m) + expf(v1 - m);
        #pragma unroll
        for (int s = 16; s; s >>= 1) e += __shfl_xor_sync(0xffffffffu, e, s);
        float lse = m + logf(e);
        float dv = (wb < 32) ? __shfl_sync(0xffffffffu, v0, wb)
                             : __shfl_sync(0xffffffffu, v1, wb - 32);
        float kt = 1.f - (float)g_mask[wb * TW + t];
        acc += kt * (dv - lse);
    }
    if (lane == 0) warp_part[wid] = acc;
    __syncthreads();
    if (threadIdx.x == 0) {
        float s = 0.f;
        #pragma unroll
        for (int k = 0; k < 8; k++) s += warp_part[k];
        g_partial[wb] = s / (nk + 1e-6f);
    }
}

__global__ void cap_loss2(float* __restrict__ out)
{
    __shared__ float sh[64];
    sh[threadIdx.x] = g_partial[threadIdx.x];
    __syncthreads();
    if (threadIdx.x == 0) {
        float s = 0.f;
        #pragma unroll
        for (int k = 0; k < 64; k++) s += sh[k];
        out[0] = -s / 64.f;
    }
}

extern "C" void kernel_launch(void* const* d_in, const int* in_sizes, int n_in,
                              void* d_out, int out_size)
{
    const float* g_o    = (const float*)d_in[0];
    const float* g_u    = (const float*)d_in[1];
    const float* g_w    = (const float*)d_in[2];
    const int*   g_mask = (const int*)d_in[3];

    float* out     = (float*)d_out;
    float* out_att = out + 1;
    float* out_avo = out_att + (size_t)BW * BO * TW * TO;

    const size_t SMEM_BYTES = (size_t)SMEM_FLOATS * sizeof(float);
    cudaFuncSetAttribute(cap_main, cudaFuncAttributeMaxDynamicSharedMemorySize,
                         (int)SMEM_BYTES);

    dim3 grid(BO, BW);
    cap_main<<<grid, NTHR, SMEM_BYTES>>>(g_o, g_u, g_w, out_att, out_avo);
    cap_loss1<<<BW, 256>>>(g_mask);
    cap_loss2<<<1, 64>>>(out);
}

// round 14
// speedup vs baseline: 1.8731x; 1.1595x over previous
#include <cuda_runtime.h>
#include <math.h>
#include <stdint.h>

#define BW 64
#define BO 64
#define TW 32
#define TO 36
#define DD 512
#define SCALE 0.044194173824159216f  // 1/sqrt(512)
#define NTHR 576

#define WHS 260     // w hi/lo word stride (words of bf16x2), 260%32=4
#define UHS 260     // u hi/lo word stride
#define OPS 520     // o-pair word stride, 520%32=8
#define ATS 28      // att word stride

// smem layout (4-byte word offsets)
#define OFF_WH   0          // 32*260 = 8320
#define OFF_WL   8320       // 8320
#define OFF_UO   16640      // region 24960: u_hi(10400)+u_lo(10400) / o_hi(12480)+o_lo(12480)
#define OFF_P2   41600      // 8*1280 = 10240
#define OFF_ATTC 51840      // 1168
#define OFF_ATH  53008      // 32*28 = 896
#define OFF_ATL  53904      // 896
#define OFF_LGP  54800      // 512
#define OFF_LGP2 55312      // 224
#define SMEM_FLOATS 55536   // 222144 bytes

__device__ float g_logits[BW * TW * BO];   // [wb][t][ob]
__device__ float g_partial[BW];

// precomputed bf16 splits (hi + residual), packed bf16x2
__device__ uint32_t d_wh[BW * TW * 256];   // [wb][t][dw]   2MB
__device__ uint32_t d_wl[BW * TW * 256];
__device__ uint32_t d_uh[BO * TO * 256];   // [ob][o][dw]   2.25MB
__device__ uint32_t d_ul[BO * TO * 256];
__device__ uint32_t d_oh[BO * 18 * 512];   // [ob][op][d] o-pair packed
__device__ uint32_t d_ol[BO * 18 * 512];

// split x,y into bf16 hi word {lo=bf16(x), hi=bf16(y)} + bf16 residual word
__device__ __forceinline__ uint32_t packsplit(float x, float y, uint32_t &lo) {
    uint32_t h;
    asm("cvt.rn.satfinite.bf16x2.f32 %0, %1, %2;" : "=r"(h) : "f"(y), "f"(x));
    float hx = __uint_as_float(h << 16);
    float hy = __uint_as_float(h & 0xffff0000u);
    float rx = x - hx, ry = y - hy;
    asm("cvt.rn.satfinite.bf16x2.f32 %0, %1, %2;" : "=r"(lo) : "f"(ry), "f"(rx));
    return h;
}
__device__ __forceinline__ float bfhalf(uint32_t w, int odd) {
    return __uint_as_float(odd ? (w & 0xffff0000u) : (w << 16));
}
__device__ __forceinline__ void mma_bf16(float* c, const uint32_t* a,
                                         uint32_t b0, uint32_t b1) {
    asm("mma.sync.aligned.m16n8k16.row.col.f32.bf16.bf16.f32 "
        "{%0,%1,%2,%3}, {%4,%5,%6,%7}, {%8,%9}, {%0,%1,%2,%3};"
        : "+f"(c[0]), "+f"(c[1]), "+f"(c[2]), "+f"(c[3])
        : "r"(a[0]), "r"(a[1]), "r"(a[2]), "r"(a[3]), "r"(b0), "r"(b1));
}

// ---------------- pre-kernel: bf16-split all inputs once --------------------
#define NW (BW * TW * 128)     // 262144 float4 tasks (w)
#define NU (BO * TO * 128)     // 294912 (u)
#define NO (BO * 18 * 128)     // 147456 (o pair-pack, 4 d per task)

__global__ void cap_prep(const float* __restrict__ g_o,
                         const float* __restrict__ g_u,
                         const float* __restrict__ g_w)
{
    int idx = blockIdx.x * blockDim.x + threadIdx.x;
    if (idx < NW) {
        float4 v = reinterpret_cast<const float4*>(g_w)[idx];
        uint32_t l0, l1;
        uint32_t h0 = packsplit(v.x, v.y, l0);
        uint32_t h1 = packsplit(v.z, v.w, l1);
        reinterpret_cast<uint2*>(d_wh)[idx] = make_uint2(h0, h1);
        reinterpret_cast<uint2*>(d_wl)[idx] = make_uint2(l0, l1);
    } else if (idx < NW + NU) {
        int j = idx - NW;
        float4 v = reinterpret_cast<const float4*>(g_u)[j];
        uint32_t l0, l1;
        uint32_t h0 = packsplit(v.x, v.y, l0);
        uint32_t h1 = packsplit(v.z, v.w, l1);
        reinterpret_cast<uint2*>(d_uh)[j] = make_uint2(h0, h1);
        reinterpret_cast<uint2*>(d_ul)[j] = make_uint2(l0, l1);
    } else if (idx < NW + NU + NO) {
        int j = idx - NW - NU;
        int bop = j >> 7, c = j & 127;        // bop = ob*18+op
        int b = bop / 18, op = bop % 18;
        const float* rA = g_o + ((size_t)(b * TO + 2 * op)) * 512 + 4 * c;
        float4 A = *reinterpret_cast<const float4*>(rA);
        float4 B = *reinterpret_cast<const float4*>(rA + 512);
        uint32_t h[4], l[4];
        h[0] = packsplit(A.x, B.x, l[0]);
        h[1] = packsplit(A.y, B.y, l[1]);
        h[2] = packsplit(A.z, B.z, l[2]);
        h[3] = packsplit(A.w, B.w, l[3]);
        *reinterpret_cast<uint4*>(&d_oh[bop * 512 + 4 * c]) = make_uint4(h[0], h[1], h[2], h[3]);
        *reinterpret_cast<uint4*>(&d_ol[bop * 512 + 4 * c]) = make_uint4(l[0], l[1], l[2], l[3]);
    }
}

extern __shared__ float smem[];

__global__ __launch_bounds__(NTHR, 1)
void cap_main(float* __restrict__ out_att,   // = d_out + 1
              float* __restrict__ out_avo)   // = d_out + 1 + 64*64*32*36
{
    const int ob  = blockIdx.x;
    const int wb  = blockIdx.y;
    const int blk = wb * BO + ob;
    const int tid = threadIdx.x;

    uint32_t* wh  = (uint32_t*)(smem + OFF_WH);
    uint32_t* wl  = (uint32_t*)(smem + OFF_WL);
    uint32_t* uh  = (uint32_t*)(smem + OFF_UO);           // phase 2
    uint32_t* ul  = uh + 10400;
    uint32_t* ohw = (uint32_t*)(smem + OFF_UO);           // phase 4 (reuse)
    uint32_t* olw = ohw + 12480;
    float*    p2     = smem + OFF_P2;
    float*    att_cs = smem + OFF_ATTC;
    uint32_t* ath    = (uint32_t*)(smem + OFF_ATH);
    uint32_t* atl    = (uint32_t*)(smem + OFF_ATL);
    float*    lgp    = smem + OFF_LGP;
    float*    lgp2   = smem + OFF_LGP2;

    const int wrp  = tid >> 5;
    const int lane = tid & 31;
    const int g    = lane >> 2;      // mma groupID
    const int tg   = lane & 3;       // mma threadID in group

    // ---------- phase 1: copy pre-split w and u tiles (pure LDG->STS) -------
    {
        const uint4* gwh = reinterpret_cast<const uint4*>(d_wh + wb * (TW * 256));
        const uint4* gwl = reinterpret_cast<const uint4*>(d_wl + wb * (TW * 256));
        for (int idx = tid; idx < TW * 64; idx += NTHR) {
            int t = idx >> 6, q = idx & 63;
            *reinterpret_cast<uint4*>(&wh[t * WHS + 4 * q]) = gwh[idx];
            *reinterpret_cast<uint4*>(&wl[t * WHS + 4 * q]) = gwl[idx];
        }
        const uint4* guh = reinterpret_cast<const uint4*>(d_uh + ob * (TO * 256));
        const uint4* gul = reinterpret_cast<const uint4*>(d_ul + ob * (TO * 256));
        for (int idx = tid; idx < TO * 64; idx += NTHR) {
            int o = idx >> 6, q = idx & 63;
            *reinterpret_cast<uint4*>(&uh[o * UHS + 4 * q]) = guh[idx];
            *reinterpret_cast<uint4*>(&ul[o * UHS + 4 * q]) = gul[idx];
        }
    }
    for (int idx = tid; idx < 4 * UHS; idx += NTHR) {   // u n-pad rows 36-39
        uh[36 * UHS + idx] = 0u;
        ul[36 * UHS + idx] = 0u;
    }
    if (tid < 192) {                                     // att k-pad words 18-23
        int r = tid / 6, j = tid % 6;
        ath[r * ATS + 18 + j] = 0u;
        atl[r * ATS + 18 + j] = 0u;
    }
    __syncthreads();

    // ---------- phase 2: scores via bf16 mma (3-term, k16) ------------------
    if (wrp < 16) {
        const int mt = wrp & 1;
        const int ks = wrp >> 1;

        float c[5][4];
        #pragma unroll
        for (int nt = 0; nt < 5; nt++)
            #pragma unroll
            for (int q = 0; q < 4; q++) c[nt][q] = 0.f;

        const uint32_t* whr0 = wh + (16 * mt + g) * WHS;
        const uint32_t* whr1 = whr0 + 8 * WHS;
        const uint32_t* wlr0 = wl + (16 * mt + g) * WHS;
        const uint32_t* wlr1 = wlr0 + 8 * WHS;

        #pragma unroll
        for (int j = 0; j < 4; j++) {
            const int kw = ks * 32 + j * 8;
            uint32_t ah[4], al[4];
            ah[0] = whr0[kw + tg];     ah[1] = whr1[kw + tg];
            ah[2] = whr0[kw + tg + 4]; ah[3] = whr1[kw + tg + 4];
            al[0] = wlr0[kw + tg];     al[1] = wlr1[kw + tg];
            al[2] = wlr0[kw + tg + 4]; al[3] = wlr1[kw + tg + 4];
            #pragma unroll
            for (int nt = 0; nt < 5; nt++) {
                const uint32_t* ur = uh + (8 * nt + g) * UHS + kw;
                const uint32_t* lr = ul + (8 * nt + g) * UHS + kw;
                uint32_t bh0 = ur[tg], bh1 = ur[tg + 4];
                uint32_t bl0 = lr[tg], bl1 = lr[tg + 4];
                mma_bf16(c[nt], ah, bh0, bh1);
                mma_bf16(c[nt], ah, bl0, bl1);
                mma_bf16(c[nt], al, bh0, bh1);
            }
        }
        float* pp = p2 + ks * 1280 + (16 * mt) * 40;
        #pragma unroll
        for (int nt = 0; nt < 5; nt++) {
            int col = 8 * nt + 2 * tg;
            *reinterpret_cast<float2*>(&pp[g * 40 + col])       = make_float2(c[nt][0], c[nt][1]);
            *reinterpret_cast<float2*>(&pp[(g + 8) * 40 + col]) = make_float2(c[nt][2], c[nt][3]);
        }
    }
    __syncthreads();

    // ---------- phase 4a (early): copy pre-split o-pair tile ----------------
    {
        const uint4* goh = reinterpret_cast<const uint4*>(d_oh + ob * (18 * 512));
        const uint4* gol = reinterpret_cast<const uint4*>(d_ol + ob * (18 * 512));
        for (int idx = tid; idx < 18 * 128; idx += NTHR) {
            int op = idx >> 7, q = idx & 127;
            *reinterpret_cast<uint4*>(&ohw[op * OPS + 4 * q]) = goh[idx];
            *reinterpret_cast<uint4*>(&olw[op * OPS + 4 * q]) = gol[idx];
        }
    }
    for (int idx = tid; idx < 6 * OPS; idx += NTHR) {    // o k-pad rows 18-23
        ohw[18 * OPS + idx] = 0u;
        olw[18 * OPS + idx] = 0u;
    }
    if (tid < 144) {                                     // o d-pad cols 512-519
        int op = tid >> 3, j = tid & 7;
        ohw[op * OPS + 512 + j] = 0u;
        olw[op * OPS + 512 + j] = 0u;
    }

    // ---------- phase 3: warp-level softmax (pair lanes, no barriers) -------
    if (wrp < 16) {
        const int row = 2 * wrp + (lane >> 4);
        const int li  = lane & 15;
        const float* pr = p2 + row * 40;
        float s0 = 0.f, s1 = 0.f, s2 = 0.f, s3 = 0.f;
        #pragma unroll
        for (int ks = 0; ks < 8; ks++) {
            float2 v = *reinterpret_cast<const float2*>(&pr[ks * 1280 + 2 * li]);
            s0 += v.x; s1 += v.y;
            if (li < 2) {
                float2 v2 = *reinterpret_cast<const float2*>(&pr[ks * 1280 + 32 + 2 * li]);
                s2 += v2.x; s3 += v2.y;
            }
        }
        s0 *= SCALE; s1 *= SCALE; s2 *= SCALE; s3 *= SCALE;
        float m = fmaxf(s0, s1);
        if (li < 2) m = fmaxf(m, fmaxf(s2, s3));
        #pragma unroll
        for (int k = 1; k < 16; k <<= 1)
            m = fmaxf(m, __shfl_xor_sync(0xffffffffu, m, k));
        float e0 = expf(s0 - m), e1 = expf(s1 - m);
        float e2 = (li < 2) ? expf(s2 - m) : 0.f;
        float e3 = (li < 2) ? expf(s3 - m) : 0.f;
        float ss = e0 + e1 + e2 + e3;
        #pragma unroll
        for (int k = 1; k < 16; k <<= 1)
            ss += __shfl_xor_sync(0xffffffffu, ss, k);
        float inv = 1.f / ss;
        float a0 = e0 * inv, a1 = e1 * inv;

        att_cs[1 + row * TO + 2 * li]     = a0;
        att_cs[1 + row * TO + 2 * li + 1] = a1;
        uint32_t lo;
        uint32_t h = packsplit(a0, a1, lo);
        ath[row * ATS + li] = h;
        atl[row * ATS + li] = lo;
        if (li < 2) {
            float a2 = e2 * inv, a3 = e3 * inv;
            att_cs[1 + row * TO + 32 + 2 * li]     = a2;
            att_cs[1 + row * TO + 32 + 2 * li + 1] = a3;
            uint32_t lo2;
            uint32_t h2 = packsplit(a2, a3, lo2);
            ath[row * ATS + 16 + li] = h2;
            atl[row * ATS + 16 + li] = lo2;
        }
    }
    __syncthreads();

    // ---------- phase 4b (warps 0-15) ∥ att store + edges (warps 16-17) -----
    if (wrp < 16) {
        const int m0 = 7 + 32 * wrp;               // warp d base

        float c[2][4][4];
        #pragma unroll
        for (int mt2 = 0; mt2 < 2; mt2++)
            #pragma unroll
            for (int nt = 0; nt < 4; nt++)
                #pragma unroll
                for (int q = 0; q < 4; q++) c[mt2][nt][q] = 0.f;

        #pragma unroll
        for (int kk = 0; kk < 3; kk++) {
            uint32_t bh[4][2], bl[4][2];
            #pragma unroll
            for (int nt = 0; nt < 4; nt++) {
                const int rb = (8 * nt + g) * ATS + 8 * kk + tg;
                bh[nt][0] = ath[rb]; bh[nt][1] = ath[rb + 4];
                bl[nt][0] = atl[rb]; bl[nt][1] = atl[rb + 4];
            }
            #pragma unroll
            for (int mt2 = 0; mt2 < 2; mt2++) {
                const int mb = m0 + 16 * mt2;
                const int base = (8 * kk + tg) * OPS + mb + g;
                uint32_t ah[4], al[4];
                ah[0] = ohw[base];           ah[1] = ohw[base + 8];
                ah[2] = ohw[base + 4 * OPS]; ah[3] = ohw[base + 4 * OPS + 8];
                al[0] = olw[base];           al[1] = olw[base + 8];
                al[2] = olw[base + 4 * OPS]; al[3] = olw[base + 4 * OPS + 8];
                #pragma unroll
                for (int nt = 0; nt < 4; nt++) {
                    mma_bf16(c[mt2][nt], ah, bh[nt][0], bh[nt][1]);
                    mma_bf16(c[mt2][nt], ah, bl[nt][0], bl[nt][1]);
                    mma_bf16(c[mt2][nt], al, bh[nt][0], bh[nt][1]);
                }
            }
        }

        float lgt[4][2];
        #pragma unroll
        for (int nt = 0; nt < 4; nt++) { lgt[nt][0] = 0.f; lgt[nt][1] = 0.f; }

        #pragma unroll
        for (int mt2 = 0; mt2 < 2; mt2++) {
            const int d0 = m0 + 16 * mt2 + g;      // d0 in [7, 511)
            const bool hi_ok = (d0 + 8 < 512);
            const int dw = d0 >> 1;
            const int odd = d0 & 1;
            #pragma unroll
            for (int nt = 0; nt < 4; nt++) {
                const int t0 = 8 * nt + 2 * tg;
                float* r0 = out_avo + ((size_t)blk * TW + t0) * DD;
                float* r1 = r0 + DD;
                r0[d0] = c[mt2][nt][0];
                r1[d0] = c[mt2][nt][1];
                float w00 = bfhalf(wh[t0 * WHS + dw], odd)       + bfhalf(wl[t0 * WHS + dw], odd);
                float w10 = bfhalf(wh[(t0 + 1) * WHS + dw], odd) + bfhalf(wl[(t0 + 1) * WHS + dw], odd);
                lgt[nt][0] += c[mt2][nt][0] * w00;
                lgt[nt][1] += c[mt2][nt][1] * w10;
                if (hi_ok) {
                    r0[d0 + 8] = c[mt2][nt][2];
                    r1[d0 + 8] = c[mt2][nt][3];
                    float w01 = bfhalf(wh[t0 * WHS + dw + 4], odd)       + bfhalf(wl[t0 * WHS + dw + 4], odd);
                    float w11 = bfhalf(wh[(t0 + 1) * WHS + dw + 4], odd) + bfhalf(wl[(t0 + 1) * WHS + dw + 4], odd);
                    lgt[nt][0] += c[mt2][nt][2] * w01;
                    lgt[nt][1] += c[mt2][nt][3] * w11;
                }
            }
        }
        // reduce over g (lane = 4g+tg): xor masks 4,8,16
        #pragma unroll
        for (int s = 4; s < 32; s <<= 1)
            #pragma unroll
            for (int nt = 0; nt < 4; nt++) {
                lgt[nt][0] += __shfl_xor_sync(0xffffffffu, lgt[nt][0], s);
                lgt[nt][1] += __shfl_xor_sync(0xffffffffu, lgt[nt][1], s);
            }
        if (g == 0) {
            #pragma unroll
            for (int nt = 0; nt < 4; nt++) {
                lgp[(8 * nt + 2 * tg)     * 16 + wrp] = lgt[nt][0];
                lgp[(8 * nt + 2 * tg + 1) * 16 + wrp] = lgt[nt][1];
            }
        }
    } else {
        // warps 16-17: att global store + edge columns d in [0,7)
        const int base = tid - 512;
        {
            const size_t ab = (size_t)blk * (TW * TO);
            for (int j = base; j < 287; j += 64) {
                float4 v = *reinterpret_cast<const float4*>(&att_cs[4 + 4 * j]);
                *reinterpret_cast<float4*>(&out_att[ab + 3 + 4 * j]) = v;
            }
            if (base == 63) {
                out_att[ab + 0]    = att_cs[1];
                out_att[ab + 1]    = att_cs[2];
                out_att[ab + 2]    = att_cs[3];
                out_att[ab + 1151] = att_cs[1152];
            }
        }
        #pragma unroll
        for (int rep = 0; rep < 4; rep++) {
            int task = base + 64 * rep;
            if (task < 224) {
                int t = task / 7, e = task % 7;
                float acc = 0.f;
                #pragma unroll 4
                for (int o = 0; o < TO; o++) {
                    int op = o >> 1, odd = o & 1;
                    float ov = bfhalf(ohw[op * OPS + e], odd) + bfhalf(olw[op * OPS + e], odd);
                    acc += att_cs[1 + t * TO + o] * ov;
                }
                out_avo[((size_t)blk * TW + t) * DD + e] = acc;
                int dw = e >> 1, odd = e & 1;
                float wv = bfhalf(wh[t * WHS + dw], odd) + bfhalf(wl[t * WHS + dw], odd);
                lgp2[task] = acc * wv;
            }
        }
    }
    __syncthreads();

    if (tid < 32) {
        float s = 0.f;
        #pragma unroll
        for (int k = 0; k < 16; k++) s += lgp[tid * 16 + k];
        #pragma unroll
        for (int e = 0; e < 7; e++)  s += lgp2[tid * 7 + e];
        g_logits[(wb * TW + tid) * BO + ob] = s;
    }
}

// log-softmax over Bo + masked diagonal accumulation, one block per wb
__global__ void cap_loss1(const int* __restrict__ g_mask)
{
    const int wb   = blockIdx.x;
    const int wid  = threadIdx.x >> 5;
    const int lane = threadIdx.x & 31;
    __shared__ float warp_part[8];

    float keepl = 1.f - (float)g_mask[wb * TW + lane];
    float nk = keepl;
    #pragma unroll
    for (int s = 16; s; s >>= 1) nk += __shfl_xor_sync(0xffffffffu, nk, s);

    float acc = 0.f;
    #pragma unroll
    for (int k = 0; k < 4; k++) {
        int t = wid + 8 * k;
        const float* row = g_logits + (wb * TW + t) * BO;
        float v0 = row[lane], v1 = row[lane + 32];
        float m = fmaxf(v0, v1);
        #pragma unroll
        for (int s = 16; s; s >>= 1) m = fmaxf(m, __shfl_xor_sync(0xffffffffu, m, s));
        float e = expf(v0 - m) + expf(v1 - m);
        #pragma unroll
        for (int s = 16; s; s >>= 1) e += __shfl_xor_sync(0xffffffffu, e, s);
        float lse = m + logf(e);
        float dv = (wb < 32) ? __shfl_sync(0xffffffffu, v0, wb)
                             : __shfl_sync(0xffffffffu, v1, wb - 32);
        float kt = 1.f - (float)g_mask[wb * TW + t];
        acc += kt * (dv - lse);
    }
    if (lane == 0) warp_part[wid] = acc;
    __syncthreads();
    if (threadIdx.x == 0) {
        float s = 0.f;
        #pragma unroll
        for (int k = 0; k < 8; k++) s += warp_part[k];
        g_partial[wb] = s / (nk + 1e-6f);
    }
}

__global__ void cap_loss2(float* __restrict__ out)
{
    __shared__ float sh[64];
    sh[threadIdx.x] = g_partial[threadIdx.x];
    __syncthreads();
    if (threadIdx.x == 0) {
        float s = 0.f;
        #pragma unroll
        for (int k = 0; k < 64; k++) s += sh[k];
        out[0] = -s / 64.f;
    }
}

extern "C" void kernel_launch(void* const* d_in, const int* in_sizes, int n_in,
                              void* d_out, int out_size)
{
    const float* g_o    = (const float*)d_in[0];
    const float* g_u    = (const float*)d_in[1];
    const float* g_w    = (const float*)d_in[2];
    const int*   g_mask = (const int*)d_in[3];

    float* out     = (float*)d_out;
    float* out_att = out + 1;
    float* out_avo = out_att + (size_t)BW * BO * TW * TO;

    const size_t SMEM_BYTES = (size_t)SMEM_FLOATS * sizeof(float);
    cudaFuncSetAttribute(cap_main, cudaFuncAttributeMaxDynamicSharedMemorySize,
                         (int)SMEM_BYTES);

    const int prep_total = NW + NU + NO;
    cap_prep<<<(prep_total + 255) / 256, 256>>>(g_o, g_u, g_w);

    dim3 grid(BO, BW);
    cap_main<<<grid, NTHR, SMEM_BYTES>>>(out_att, out_avo);
    cap_loss1<<<BW, 256>>>(g_mask);
    cap_loss2<<<1, 64>>>(out);
}

// round 15
// speedup vs baseline: 2.0730x; 1.1067x over previous
#include <cuda_runtime.h>
#include <math.h>
#include <stdint.h>

#define BW 64
#define BO 64
#define TW 32
#define TO 36
#define DD 512
#define SCALE 0.044194173824159216f  // 1/sqrt(512)
#define NTHR 576
#define NCTA 148
#define NTILE (BW * BO)

#define WHS 260     // w hi/lo word stride (words of bf16x2), 260%32=4
#define UHS 260     // u hi/lo word stride
#define OPS 520     // o-pair word stride, 520%32=8
#define ATS 28      // att word stride

// smem layout (4-byte word offsets)
#define OFF_WH   0          // 32*260 = 8320
#define OFF_WL   8320       // 8320
#define OFF_UO   16640      // region 24960: u_hi(10400)+u_lo(10400) / o_hi(12480)+o_lo(12480)
#define OFF_P2   41600      // 8*1280 = 10240
#define OFF_ATTC 51840      // 1168
#define OFF_ATH  53008      // 32*28 = 896
#define OFF_ATL  53904      // 896
#define OFF_LGP  54800      // 512
#define OFF_LGP2 55312      // 224
#define SMEM_FLOATS 55536   // 222144 bytes

__device__ float g_logits[BW * TW * BO];   // [wb][t][ob]
__device__ float g_partial[BW];

// precomputed bf16 splits (hi + residual), packed bf16x2
__device__ uint32_t d_wh[BW * TW * 256];   // [wb][t][dw]
__device__ uint32_t d_wl[BW * TW * 256];
__device__ uint32_t d_uh[BO * TO * 256];   // [ob][o][dw]
__device__ uint32_t d_ul[BO * TO * 256];
__device__ uint32_t d_oh[BO * 18 * 512];   // [ob][op][d] o-pair packed
__device__ uint32_t d_ol[BO * 18 * 512];

// split x,y into bf16 hi word {lo=bf16(x), hi=bf16(y)} + bf16 residual word
__device__ __forceinline__ uint32_t packsplit(float x, float y, uint32_t &lo) {
    uint32_t h;
    asm("cvt.rn.satfinite.bf16x2.f32 %0, %1, %2;" : "=r"(h) : "f"(y), "f"(x));
    float hx = __uint_as_float(h << 16);
    float hy = __uint_as_float(h & 0xffff0000u);
    float rx = x - hx, ry = y - hy;
    asm("cvt.rn.satfinite.bf16x2.f32 %0, %1, %2;" : "=r"(lo) : "f"(ry), "f"(rx));
    return h;
}
__device__ __forceinline__ float bfhalf(uint32_t w, int odd) {
    return __uint_as_float(odd ? (w & 0xffff0000u) : (w << 16));
}
__device__ __forceinline__ void mma_bf16(float* c, const uint32_t* a,
                                         uint32_t b0, uint32_t b1) {
    asm("mma.sync.aligned.m16n8k16.row.col.f32.bf16.bf16.f32 "
        "{%0,%1,%2,%3}, {%4,%5,%6,%7}, {%8,%9}, {%0,%1,%2,%3};"
        : "+f"(c[0]), "+f"(c[1]), "+f"(c[2]), "+f"(c[3])
        : "r"(a[0]), "r"(a[1]), "r"(a[2]), "r"(a[3]), "r"(b0), "r"(b1));
}

// ---------------- pre-kernel: bf16-split all inputs once --------------------
#define NW (BW * TW * 128)
#define NU (BO * TO * 128)
#define NO (BO * 18 * 128)

__global__ void cap_prep(const float* __restrict__ g_o,
                         const float* __restrict__ g_u,
                         const float* __restrict__ g_w)
{
    int idx = blockIdx.x * blockDim.x + threadIdx.x;
    if (idx < NW) {
        float4 v = reinterpret_cast<const float4*>(g_w)[idx];
        uint32_t l0, l1;
        uint32_t h0 = packsplit(v.x, v.y, l0);
        uint32_t h1 = packsplit(v.z, v.w, l1);
        reinterpret_cast<uint2*>(d_wh)[idx] = make_uint2(h0, h1);
        reinterpret_cast<uint2*>(d_wl)[idx] = make_uint2(l0, l1);
    } else if (idx < NW + NU) {
        int j = idx - NW;
        float4 v = reinterpret_cast<const float4*>(g_u)[j];
        uint32_t l0, l1;
        uint32_t h0 = packsplit(v.x, v.y, l0);
        uint32_t h1 = packsplit(v.z, v.w, l1);
        reinterpret_cast<uint2*>(d_uh)[j] = make_uint2(h0, h1);
        reinterpret_cast<uint2*>(d_ul)[j] = make_uint2(l0, l1);
    } else if (idx < NW + NU + NO) {
        int j = idx - NW - NU;
        int bop = j >> 7, c = j & 127;        // bop = ob*18+op
        int b = bop / 18, op = bop % 18;
        const float* rA = g_o + ((size_t)(b * TO + 2 * op)) * 512 + 4 * c;
        float4 A = *reinterpret_cast<const float4*>(rA);
        float4 B = *reinterpret_cast<const float4*>(rA + 512);
        uint32_t h[4], l[4];
        h[0] = packsplit(A.x, B.x, l[0]);
        h[1] = packsplit(A.y, B.y, l[1]);
        h[2] = packsplit(A.z, B.z, l[2]);
        h[3] = packsplit(A.w, B.w, l[3]);
        *reinterpret_cast<uint4*>(&d_oh[bop * 512 + 4 * c]) = make_uint4(h[0], h[1], h[2], h[3]);
        *reinterpret_cast<uint4*>(&d_ol[bop * 512 + 4 * c]) = make_uint4(l[0], l[1], l[2], l[3]);
    }
}

extern __shared__ float smem[];

__global__ __launch_bounds__(NTHR, 1)
void cap_main(float* __restrict__ out_att,   // = d_out + 1
              float* __restrict__ out_avo)   // = d_out + 1 + 64*64*32*36
{
    const int tid = threadIdx.x;

    uint32_t* wh  = (uint32_t*)(smem + OFF_WH);
    uint32_t* wl  = (uint32_t*)(smem + OFF_WL);
    uint32_t* uh  = (uint32_t*)(smem + OFF_UO);           // phase 2
    uint32_t* ul  = uh + 10400;
    uint32_t* ohw = (uint32_t*)(smem + OFF_UO);           // phase 4 (reuse)
    uint32_t* olw = ohw + 12480;
    float*    p2     = smem + OFF_P2;
    float*    att_cs = smem + OFF_ATTC;
    uint32_t* ath    = (uint32_t*)(smem + OFF_ATH);
    uint32_t* atl    = (uint32_t*)(smem + OFF_ATL);
    float*    lgp    = smem + OFF_LGP;
    float*    lgp2   = smem + OFF_LGP2;

    const int wrp  = tid >> 5;
    const int lane = tid & 31;
    const int g    = lane >> 2;      // mma groupID
    const int tg   = lane & 3;       // mma threadID in group

    // persistent chunked schedule: CTA owns tiles [t0, t1)
    const int per = (NTILE + NCTA - 1) / NCTA;           // 28
    const int t0c = blockIdx.x * per;
    const int t1c = (t0c + per < NTILE) ? (t0c + per) : NTILE;

    // att k-pad words 18-23: region untouched by loop bodies -> hoisted
    if (tid < 192) {
        int r = tid / 6, j = tid % 6;
        ath[r * ATS + 18 + j] = 0u;
        atl[r * ATS + 18 + j] = 0u;
    }

    int prev_wb = -1;
    for (int tile = t0c; tile < t1c; tile++) {
        const int wb  = tile >> 6;
        const int ob  = tile & 63;
        const int blk = tile;

        // ---------- phase 1: copy pre-split w (if wb changed) and u ---------
        if (wb != prev_wb) {
            const uint4* gwh = reinterpret_cast<const uint4*>(d_wh + wb * (TW * 256));
            const uint4* gwl = reinterpret_cast<const uint4*>(d_wl + wb * (TW * 256));
            for (int idx = tid; idx < TW * 64; idx += NTHR) {
                int t = idx >> 6, q = idx & 63;
                *reinterpret_cast<uint4*>(&wh[t * WHS + 4 * q]) = gwh[idx];
                *reinterpret_cast<uint4*>(&wl[t * WHS + 4 * q]) = gwl[idx];
            }
        }
        prev_wb = wb;
        {
            const uint4* guh = reinterpret_cast<const uint4*>(d_uh + ob * (TO * 256));
            const uint4* gul = reinterpret_cast<const uint4*>(d_ul + ob * (TO * 256));
            for (int idx = tid; idx < TO * 64; idx += NTHR) {
                int o = idx >> 6, q = idx & 63;
                *reinterpret_cast<uint4*>(&uh[o * UHS + 4 * q]) = guh[idx];
                *reinterpret_cast<uint4*>(&ul[o * UHS + 4 * q]) = gul[idx];
            }
        }
        for (int idx = tid; idx < 4 * UHS; idx += NTHR) {   // u n-pad rows 36-39
            uh[36 * UHS + idx] = 0u;
            ul[36 * UHS + idx] = 0u;
        }
        __syncthreads();

        // ---------- phase 2: scores via bf16 mma (3-term, k16) --------------
        if (wrp < 16) {
            const int mt = wrp & 1;
            const int ks = wrp >> 1;

            float c[5][4];
            #pragma unroll
            for (int nt = 0; nt < 5; nt++)
                #pragma unroll
                for (int q = 0; q < 4; q++) c[nt][q] = 0.f;

            const uint32_t* whr0 = wh + (16 * mt + g) * WHS;
            const uint32_t* whr1 = whr0 + 8 * WHS;
            const uint32_t* wlr0 = wl + (16 * mt + g) * WHS;
            const uint32_t* wlr1 = wlr0 + 8 * WHS;

            #pragma unroll
            for (int j = 0; j < 4; j++) {
                const int kw = ks * 32 + j * 8;
                uint32_t ah[4], al[4];
                ah[0] = whr0[kw + tg];     ah[1] = whr1[kw + tg];
                ah[2] = whr0[kw + tg + 4]; ah[3] = whr1[kw + tg + 4];
                al[0] = wlr0[kw + tg];     al[1] = wlr1[kw + tg];
                al[2] = wlr0[kw + tg + 4]; al[3] = wlr1[kw + tg + 4];
                #pragma unroll
                for (int nt = 0; nt < 5; nt++) {
                    const uint32_t* ur = uh + (8 * nt + g) * UHS + kw;
                    const uint32_t* lr = ul + (8 * nt + g) * UHS + kw;
                    uint32_t bh0 = ur[tg], bh1 = ur[tg + 4];
                    uint32_t bl0 = lr[tg], bl1 = lr[tg + 4];
                    mma_bf16(c[nt], ah, bh0, bh1);
                    mma_bf16(c[nt], ah, bl0, bl1);
                    mma_bf16(c[nt], al, bh0, bh1);
                }
            }
            float* pp = p2 + ks * 1280 + (16 * mt) * 40;
            #pragma unroll
            for (int nt = 0; nt < 5; nt++) {
                int col = 8 * nt + 2 * tg;
                *reinterpret_cast<float2*>(&pp[g * 40 + col])       = make_float2(c[nt][0], c[nt][1]);
                *reinterpret_cast<float2*>(&pp[(g + 8) * 40 + col]) = make_float2(c[nt][2], c[nt][3]);
            }
        }
        __syncthreads();

        // ---------- phase 4a (early): copy pre-split o-pair tile ------------
        {
            const uint4* goh = reinterpret_cast<const uint4*>(d_oh + ob * (18 * 512));
            const uint4* gol = reinterpret_cast<const uint4*>(d_ol + ob * (18 * 512));
            for (int idx = tid; idx < 18 * 128; idx += NTHR) {
                int op = idx >> 7, q = idx & 127;
                *reinterpret_cast<uint4*>(&ohw[op * OPS + 4 * q]) = goh[idx];
                *reinterpret_cast<uint4*>(&olw[op * OPS + 4 * q]) = gol[idx];
            }
        }
        for (int idx = tid; idx < 6 * OPS; idx += NTHR) {    // o k-pad rows 18-23
            ohw[18 * OPS + idx] = 0u;
            olw[18 * OPS + idx] = 0u;
        }
        if (tid < 144) {                                     // o d-pad cols 512-519
            int op = tid >> 3, j = tid & 7;
            ohw[op * OPS + 512 + j] = 0u;
            olw[op * OPS + 512 + j] = 0u;
        }

        // ---------- phase 3: warp-level softmax (no barriers) ---------------
        if (wrp < 16) {
            const int row = 2 * wrp + (lane >> 4);
            const int li  = lane & 15;
            const float* pr = p2 + row * 40;
            float s0 = 0.f, s1 = 0.f, s2 = 0.f, s3 = 0.f;
            #pragma unroll
            for (int ks = 0; ks < 8; ks++) {
                float2 v = *reinterpret_cast<const float2*>(&pr[ks * 1280 + 2 * li]);
                s0 += v.x; s1 += v.y;
                if (li < 2) {
                    float2 v2 = *reinterpret_cast<const float2*>(&pr[ks * 1280 + 32 + 2 * li]);
                    s2 += v2.x; s3 += v2.y;
                }
            }
            s0 *= SCALE; s1 *= SCALE; s2 *= SCALE; s3 *= SCALE;
            float m = fmaxf(s0, s1);
            if (li < 2) m = fmaxf(m, fmaxf(s2, s3));
            #pragma unroll
            for (int k = 1; k < 16; k <<= 1)
                m = fmaxf(m, __shfl_xor_sync(0xffffffffu, m, k));
            float e0 = expf(s0 - m), e1 = expf(s1 - m);
            float e2 = (li < 2) ? expf(s2 - m) : 0.f;
            float e3 = (li < 2) ? expf(s3 - m) : 0.f;
            float ss = e0 + e1 + e2 + e3;
            #pragma unroll
            for (int k = 1; k < 16; k <<= 1)
                ss += __shfl_xor_sync(0xffffffffu, ss, k);
            float inv = 1.f / ss;
            float a0 = e0 * inv, a1 = e1 * inv;

            att_cs[1 + row * TO + 2 * li]     = a0;
            att_cs[1 + row * TO + 2 * li + 1] = a1;
            uint32_t lo;
            uint32_t h = packsplit(a0, a1, lo);
            ath[row * ATS + li] = h;
            atl[row * ATS + li] = lo;
            if (li < 2) {
                float a2 = e2 * inv, a3 = e3 * inv;
                att_cs[1 + row * TO + 32 + 2 * li]     = a2;
                att_cs[1 + row * TO + 32 + 2 * li + 1] = a3;
                uint32_t lo2;
                uint32_t h2 = packsplit(a2, a3, lo2);
                ath[row * ATS + 16 + li] = h2;
                atl[row * ATS + 16 + li] = lo2;
            }
        }
        __syncthreads();

        // ---------- phase 4b (warps 0-15) ∥ att store + edges (16-17) -------
        if (wrp < 16) {
            const int m0 = 7 + 32 * wrp;               // warp d base

            float c[2][4][4];
            #pragma unroll
            for (int mt2 = 0; mt2 < 2; mt2++)
                #pragma unroll
                for (int nt = 0; nt < 4; nt++)
                    #pragma unroll
                    for (int q = 0; q < 4; q++) c[mt2][nt][q] = 0.f;

            #pragma unroll
            for (int kk = 0; kk < 3; kk++) {
                uint32_t bh[4][2], bl[4][2];
                #pragma unroll
                for (int nt = 0; nt < 4; nt++) {
                    const int rb = (8 * nt + g) * ATS + 8 * kk + tg;
                    bh[nt][0] = ath[rb]; bh[nt][1] = ath[rb + 4];
                    bl[nt][0] = atl[rb]; bl[nt][1] = atl[rb + 4];
                }
                #pragma unroll
                for (int mt2 = 0; mt2 < 2; mt2++) {
                    const int mb = m0 + 16 * mt2;
                    const int base = (8 * kk + tg) * OPS + mb + g;
                    uint32_t ah[4], al[4];
                    ah[0] = ohw[base];           ah[1] = ohw[base + 8];
                    ah[2] = ohw[base + 4 * OPS]; ah[3] = ohw[base + 4 * OPS + 8];
                    al[0] = olw[base];           al[1] = olw[base + 8];
                    al[2] = olw[base + 4 * OPS]; al[3] = olw[base + 4 * OPS + 8];
                    #pragma unroll
                    for (int nt = 0; nt < 4; nt++) {
                        mma_bf16(c[mt2][nt], ah, bh[nt][0], bh[nt][1]);
                        mma_bf16(c[mt2][nt], ah, bl[nt][0], bl[nt][1]);
                        mma_bf16(c[mt2][nt], al, bh[nt][0], bh[nt][1]);
                    }
                }
            }

            float lgt[4][2];
            #pragma unroll
            for (int nt = 0; nt < 4; nt++) { lgt[nt][0] = 0.f; lgt[nt][1] = 0.f; }

            #pragma unroll
            for (int mt2 = 0; mt2 < 2; mt2++) {
                const int d0 = m0 + 16 * mt2 + g;      // d0 in [7, 511)
                const bool hi_ok = (d0 + 8 < 512);
                const int dw = d0 >> 1;
                const int odd = d0 & 1;
                #pragma unroll
                for (int nt = 0; nt < 4; nt++) {
                    const int t0 = 8 * nt + 2 * tg;
                    float* r0 = out_avo + ((size_t)blk * TW + t0) * DD;
                    float* r1 = r0 + DD;
                    r0[d0] = c[mt2][nt][0];
                    r1[d0] = c[mt2][nt][1];
                    float w00 = bfhalf(wh[t0 * WHS + dw], odd)       + bfhalf(wl[t0 * WHS + dw], odd);
                    float w10 = bfhalf(wh[(t0 + 1) * WHS + dw], odd) + bfhalf(wl[(t0 + 1) * WHS + dw], odd);
                    lgt[nt][0] += c[mt2][nt][0] * w00;
                    lgt[nt][1] += c[mt2][nt][1] * w10;
                    if (hi_ok) {
                        r0[d0 + 8] = c[mt2][nt][2];
                        r1[d0 + 8] = c[mt2][nt][3];
                        float w01 = bfhalf(wh[t0 * WHS + dw + 4], odd)       + bfhalf(wl[t0 * WHS + dw + 4], odd);
                        float w11 = bfhalf(wh[(t0 + 1) * WHS + dw + 4], odd) + bfhalf(wl[(t0 + 1) * WHS + dw + 4], odd);
                        lgt[nt][0] += c[mt2][nt][2] * w01;
                        lgt[nt][1] += c[mt2][nt][3] * w11;
                    }
                }
            }
            #pragma unroll
            for (int s = 4; s < 32; s <<= 1)
                #pragma unroll
                for (int nt = 0; nt < 4; nt++) {
                    lgt[nt][0] += __shfl_xor_sync(0xffffffffu, lgt[nt][0], s);
                    lgt[nt][1] += __shfl_xor_sync(0xffffffffu, lgt[nt][1], s);
                }
            if (g == 0) {
                #pragma unroll
                for (int nt = 0; nt < 4; nt++) {
                    lgp[(8 * nt + 2 * tg)     * 16 + wrp] = lgt[nt][0];
                    lgp[(8 * nt + 2 * tg + 1) * 16 + wrp] = lgt[nt][1];
                }
            }
        } else {
            // warps 16-17: att global store + edge columns d in [0,7)
            const int base = tid - 512;
            {
                const size_t ab = (size_t)blk * (TW * TO);
                for (int j = base; j < 287; j += 64) {
                    float4 v = *reinterpret_cast<const float4*>(&att_cs[4 + 4 * j]);
                    *reinterpret_cast<float4*>(&out_att[ab + 3 + 4 * j]) = v;
                }
                if (base == 63) {
                    out_att[ab + 0]    = att_cs[1];
                    out_att[ab + 1]    = att_cs[2];
                    out_att[ab + 2]    = att_cs[3];
                    out_att[ab + 1151] = att_cs[1152];
                }
            }
            #pragma unroll
            for (int rep = 0; rep < 4; rep++) {
                int task = base + 64 * rep;
                if (task < 224) {
                    int t = task / 7, e = task % 7;
                    float acc = 0.f;
                    #pragma unroll 4
                    for (int o = 0; o < TO; o++) {
                        int op = o >> 1, odd = o & 1;
                        float ov = bfhalf(ohw[op * OPS + e], odd) + bfhalf(olw[op * OPS + e], odd);
                        acc += att_cs[1 + t * TO + o] * ov;
                    }
                    out_avo[((size_t)blk * TW + t) * DD + e] = acc;
                    int dw = e >> 1, odd = e & 1;
                    float wv = bfhalf(wh[t * WHS + dw], odd) + bfhalf(wl[t * WHS + dw], odd);
                    lgp2[task] = acc * wv;
                }
            }
        }
        __syncthreads();

        if (tid < 32) {
            float s = 0.f;
            #pragma unroll
            for (int k = 0; k < 16; k++) s += lgp[tid * 16 + k];
            #pragma unroll
            for (int e = 0; e < 7; e++)  s += lgp2[tid * 7 + e];
            g_logits[(wb * TW + tid) * BO + ob] = s;
        }
    }
}

// log-softmax over Bo + masked diagonal accumulation, one block per wb
__global__ void cap_loss1(const int* __restrict__ g_mask)
{
    const int wb   = blockIdx.x;
    const int wid  = threadIdx.x >> 5;
    const int lane = threadIdx.x & 31;
    __shared__ float warp_part[8];

    float keepl = 1.f - (float)g_mask[wb * TW + lane];
    float nk = keepl;
    #pragma unroll
    for (int s = 16; s; s >>= 1) nk += __shfl_xor_sync(0xffffffffu, nk, s);

    float acc = 0.f;
    #pragma unroll
    for (int k = 0; k < 4; k++) {
        int t = wid + 8 * k;
        const float* row = g_logits + (wb * TW + t) * BO;
        float v0 = row[lane], v1 = row[lane + 32];
        float m = fmaxf(v0, v1);
        #pragma unroll
        for (int s = 16; s; s >>= 1) m = fmaxf(m, __shfl_xor_sync(0xffffffffu, m, s));
        float e = expf(v0 - m) + expf(v1 - m);
        #pragma unroll
        for (int s = 16; s; s >>= 1) e += __shfl_xor_sync(0xffffffffu, e, s);
        float lse = m + logf(e);
        float dv = (wb < 32) ? __shfl_sync(0xffffffffu, v0, wb)
                             : __shfl_sync(0xffffffffu, v1, wb - 32);
        float kt = 1.f - (float)g_mask[wb * TW + t];
        acc += kt * (dv - lse);
    }
    if (lane == 0) warp_part[wid] = acc;
    __syncthreads();
    if (threadIdx.x == 0) {
        float s = 0.f;
        #pragma unroll
        for (int k = 0; k < 8; k++) s += warp_part[k];
        g_partial[wb] = s / (nk + 1e-6f);
    }
}

__global__ void cap_loss2(float* __restrict__ out)
{
    __shared__ float sh[64];
    sh[threadIdx.x] = g_partial[threadIdx.x];
    __syncthreads();
    if (threadIdx.x == 0) {
        float s = 0.f;
        #pragma unroll
        for (int k = 0; k < 64; k++) s += sh[k];
        out[0] = -s / 64.f;
    }
}

extern "C" void kernel_launch(void* const* d_in, const int* in_sizes, int n_in,
                              void* d_out, int out_size)
{
    const float* g_o    = (const float*)d_in[0];
    const float* g_u    = (const float*)d_in[1];
    const float* g_w    = (const float*)d_in[2];
    const int*   g_mask = (const int*)d_in[3];

    float* out     = (float*)d_out;
    float* out_att = out + 1;
    float* out_avo = out_att + (size_t)BW * BO * TW * TO;

    const size_t SMEM_BYTES = (size_t)SMEM_FLOATS * sizeof(float);
    cudaFuncSetAttribute(cap_main, cudaFuncAttributeMaxDynamicSharedMemorySize,
                         (int)SMEM_BYTES);

    const int prep_total = NW + NU + NO;
    cap_prep<<<(prep_total + 255) / 256, 256>>>(g_o, g_u, g_w);

    cap_main<<<NCTA, NTHR, SMEM_BYTES>>>(out_att, out_avo);
    cap_loss1<<<BW, 256>>>(g_mask);
    cap_loss2<<<1, 64>>>(out);
}